// round 3
// baseline (speedup 1.0000x reference)
#include <cuda_runtime.h>
#include <cstdint>

// ---------------- problem constants ----------------
#define NB   8
#define NL   4096
#define NDIM 768
#define NH   12
#define ND   64
#define NM   256           // feature dim
#define NTOK (NB * NL)     // 32768
#define NRH  (NTOK * NH)   // 393216  (token*head rows for feature GEMM)
#define KV_N 65            // 64 v-dims + 1 ones-column (k_sum)
#define FEPS 1.0e-3f
#define RATIO 0.0625f      // 1/sqrt(256)

// ---------------- scratch (static device globals; no allocs) ----------------
__device__ float g_qkv[(size_t)NTOK * 3 * NDIM];   // 302 MB  (q|k|v per token)
__device__ float g_qp [(size_t)NRH * NM];          // 402 MB  (B,L,H,M)
__device__ float g_kp [(size_t)NRH * NM];          // 402 MB
__device__ float g_kv [(size_t)NB * NH * NM * KV_N]; // 6.4 MB  (kv | k_sum)
__device__ float g_att[(size_t)NTOK * NDIM];       // 100 MB  (pre-proj output)

// ---------------- K0: zero the kv accumulator ----------------
__global__ void zero_kernel(float* __restrict__ p, int n) {
    int i = blockIdx.x * blockDim.x + threadIdx.x;
    if (i < n) p[i] = 0.0f;
}

// ---------------- K1/K5: C[M,N] = A[M,K] * B[N,K]^T + bias[N] ----------------
// 128x128 tile, BK=16, 256 threads, 8x8 microtile. M%128==0, N%128==0, K%16==0.
__global__ __launch_bounds__(256) void sgemm_nt_bias(
    const float* __restrict__ A, const float* __restrict__ B,
    const float* __restrict__ bias, float* __restrict__ C,
    int N, int K)
{
    __shared__ float As[16][132];   // [k][m], stride-132 pad (16B-aligned rows)
    __shared__ float Bs[16][132];   // [k][n]
    const int tid = threadIdx.x;
    const int tx = tid & 15, ty = tid >> 4;
    const int m0 = blockIdx.y * 128, n0 = blockIdx.x * 128;

    float acc[8][8];
#pragma unroll
    for (int i = 0; i < 8; i++)
#pragma unroll
        for (int j = 0; j < 8; j++) acc[i][j] = 0.0f;

    for (int k0 = 0; k0 < K; k0 += 16) {
#pragma unroll
        for (int it = 0; it < 2; it++) {
            int lin = tid + it * 256;
            int row = lin >> 2;           // 0..127
            int kg  = (lin & 3) << 2;     // 0,4,8,12
            float4 va = *(const float4*)(A + (size_t)(m0 + row) * K + k0 + kg);
            As[kg+0][row] = va.x; As[kg+1][row] = va.y;
            As[kg+2][row] = va.z; As[kg+3][row] = va.w;
            float4 vb = *(const float4*)(B + (size_t)(n0 + row) * K + k0 + kg);
            Bs[kg+0][row] = vb.x; Bs[kg+1][row] = vb.y;
            Bs[kg+2][row] = vb.z; Bs[kg+3][row] = vb.w;
        }
        __syncthreads();
#pragma unroll
        for (int kk = 0; kk < 16; kk++) {
            float a[8], b[8];
            *(float4*)&a[0] = *(const float4*)&As[kk][ty * 8];
            *(float4*)&a[4] = *(const float4*)&As[kk][ty * 8 + 4];
            *(float4*)&b[0] = *(const float4*)&Bs[kk][tx * 8];
            *(float4*)&b[4] = *(const float4*)&Bs[kk][tx * 8 + 4];
#pragma unroll
            for (int i = 0; i < 8; i++)
#pragma unroll
                for (int j = 0; j < 8; j++) acc[i][j] += a[i] * b[j];
        }
        __syncthreads();
    }

#pragma unroll
    for (int i = 0; i < 8; i++) {
        int row = m0 + ty * 8 + i;
        float* cp = C + (size_t)row * N + n0 + tx * 8;
#pragma unroll
        for (int j = 0; j < 8; j++) acc[i][j] += bias[n0 + tx * 8 + j];
        float4 o0 = make_float4(acc[i][0], acc[i][1], acc[i][2], acc[i][3]);
        float4 o1 = make_float4(acc[i][4], acc[i][5], acc[i][6], acc[i][7]);
        *(float4*)cp       = o0;
        *(float4*)(cp + 4) = o1;
    }
}

// ---------------- K2: feature projection q_p / k_p ----------------
// rows = (token,head) pairs (NRH), cols = NM, K = ND (64).
// A[rh, d] = g_qkv[token*2304 + qoff + head*64 + d]; epilogue relu(ratio*z)+eps.
__global__ __launch_bounds__(256) void feature_kernel(const float* __restrict__ pm)
{
    __shared__ float As[16][132];
    __shared__ float Bs[16][132];
    const int tid = threadIdx.x;
    const int tx = tid & 15, ty = tid >> 4;
    const int m0 = blockIdx.y * 128, n0 = blockIdx.x * 128;
    const int qoff = blockIdx.z ? NDIM : 0;
    float* __restrict__ out = blockIdx.z ? g_kp : g_qp;

    float acc[8][8];
#pragma unroll
    for (int i = 0; i < 8; i++)
#pragma unroll
        for (int j = 0; j < 8; j++) acc[i][j] = 0.0f;

    for (int k0 = 0; k0 < ND; k0 += 16) {
#pragma unroll
        for (int it = 0; it < 2; it++) {
            int lin = tid + it * 256;
            int row = lin >> 2;
            int kg  = (lin & 3) << 2;
            int rh = m0 + row;
            int r  = rh / NH;
            int h  = rh - r * NH;
            float4 va = *(const float4*)(g_qkv + (size_t)r * (3 * NDIM) + qoff + h * ND + k0 + kg);
            As[kg+0][row] = va.x; As[kg+1][row] = va.y;
            As[kg+2][row] = va.z; As[kg+3][row] = va.w;
            float4 vb = *(const float4*)(pm + (size_t)(n0 + row) * ND + k0 + kg);
            Bs[kg+0][row] = vb.x; Bs[kg+1][row] = vb.y;
            Bs[kg+2][row] = vb.z; Bs[kg+3][row] = vb.w;
        }
        __syncthreads();
#pragma unroll
        for (int kk = 0; kk < 16; kk++) {
            float a[8], b[8];
            *(float4*)&a[0] = *(const float4*)&As[kk][ty * 8];
            *(float4*)&a[4] = *(const float4*)&As[kk][ty * 8 + 4];
            *(float4*)&b[0] = *(const float4*)&Bs[kk][tx * 8];
            *(float4*)&b[4] = *(const float4*)&Bs[kk][tx * 8 + 4];
#pragma unroll
            for (int i = 0; i < 8; i++)
#pragma unroll
                for (int j = 0; j < 8; j++) acc[i][j] += a[i] * b[j];
        }
        __syncthreads();
    }

#pragma unroll
    for (int i = 0; i < 8; i++) {
        int rh = m0 + ty * 8 + i;
        float* cp = out + (size_t)rh * NM + n0 + tx * 8;
        float o[8];
#pragma unroll
        for (int j = 0; j < 8; j++)
            o[j] = fmaxf(acc[i][j] * RATIO, 0.0f) + FEPS;
        *(float4*)cp       = make_float4(o[0], o[1], o[2], o[3]);
        *(float4*)(cp + 4) = make_float4(o[4], o[5], o[6], o[7]);
    }
}

// ---------------- K3: kv_ext[b,h] = k_p^T @ [v | 1]  (accumulate via atomics) ----------------
// grid: (NB*NH, NL/512). Each block: 512 tokens, thread m owns kv row m (65 cols).
__global__ __launch_bounds__(256) void kv_kernel()
{
    const int bh = blockIdx.x;
    const int b = bh / NH, h = bh - b * NH;
    const int l0 = blockIdx.y * 512;
    const int m = threadIdx.x;

    __shared__ float4 v_sh[8][16];   // 8 tokens x 64 v-dims

    float acc[KV_N];
#pragma unroll
    for (int d = 0; d < KV_N; d++) acc[d] = 0.0f;

    const size_t v_base = (size_t)(b * NL + l0) * (3 * NDIM) + 2 * NDIM + h * ND;
    const size_t kp_base = ((size_t)(b * NL + l0) * NH + h) * NM + m;

    for (int li = 0; li < 512; li += 8) {
        if (threadIdx.x < 128) {
            int row = threadIdx.x >> 4;
            int dg  = threadIdx.x & 15;
            v_sh[row][dg] = *(const float4*)(g_qkv + v_base + (size_t)(li + row) * (3 * NDIM) + dg * 4);
        }
        __syncthreads();
#pragma unroll
        for (int j = 0; j < 8; j++) {
            float kp = g_kp[kp_base + (size_t)(li + j) * NH * NM];
#pragma unroll
            for (int dg = 0; dg < 16; dg++) {
                float4 v4 = v_sh[j][dg];
                acc[dg*4+0] += kp * v4.x;
                acc[dg*4+1] += kp * v4.y;
                acc[dg*4+2] += kp * v4.z;
                acc[dg*4+3] += kp * v4.w;
            }
            acc[64] += kp;   // ones column -> k_sum
        }
        __syncthreads();
    }

    float* outp = g_kv + ((size_t)bh * NM + m) * KV_N;
#pragma unroll
    for (int d = 0; d < KV_N; d++) atomicAdd(&outp[d], acc[d]);
}

// ---------------- K4: num = q_p @ kv, den = q_p @ k_sum, att = num/den ----------------
// grid (NL/128, NH, NB); 256 threads (16x16), each thread 8 rows x 4 cols.
__global__ __launch_bounds__(256) void attn_out_kernel()
{
    const int b = blockIdx.z, h = blockIdx.y;
    const int r0 = b * NL + blockIdx.x * 128;   // global token row
    const int tid = threadIdx.x;
    const int tx = tid & 15, ty = tid >> 4;

    __shared__ float q_sh[32][132];   // [k][l]
    __shared__ float kv_sh[32][68];   // [k][n], 65 used
    __shared__ float den_sh[128];

    float acc[8][4];
    float dacc[8];
#pragma unroll
    for (int i = 0; i < 8; i++) {
        dacc[i] = 0.0f;
#pragma unroll
        for (int j = 0; j < 4; j++) acc[i][j] = 0.0f;
    }

    const float* kvb = g_kv + (size_t)(b * NH + h) * NM * KV_N;

    for (int k0 = 0; k0 < NM; k0 += 32) {
        for (int idx = tid; idx < 32 * KV_N; idx += 256) {
            int k = idx / KV_N, n = idx - k * KV_N;
            kv_sh[k][n] = kvb[(size_t)(k0 + k) * KV_N + n];
        }
#pragma unroll
        for (int it = 0; it < 4; it++) {
            int lin = tid + it * 256;
            int row = lin >> 3;            // 0..127
            int kg  = (lin & 7) << 2;      // 0..28
            float4 v = *(const float4*)(g_qp + ((size_t)(r0 + row) * NH + h) * NM + k0 + kg);
            q_sh[kg+0][row] = v.x; q_sh[kg+1][row] = v.y;
            q_sh[kg+2][row] = v.z; q_sh[kg+3][row] = v.w;
        }
        __syncthreads();
#pragma unroll
        for (int k = 0; k < 32; k++) {
            float a[8];
            *(float4*)&a[0] = *(const float4*)&q_sh[k][ty * 8];
            *(float4*)&a[4] = *(const float4*)&q_sh[k][ty * 8 + 4];
            float4 bv = *(const float4*)&kv_sh[k][tx * 4];
#pragma unroll
            for (int i = 0; i < 8; i++) {
                acc[i][0] += a[i] * bv.x;
                acc[i][1] += a[i] * bv.y;
                acc[i][2] += a[i] * bv.z;
                acc[i][3] += a[i] * bv.w;
            }
            if (tx == 0) {
                float ks = kv_sh[k][64];
#pragma unroll
                for (int i = 0; i < 8; i++) dacc[i] += a[i] * ks;
            }
        }
        __syncthreads();
    }

    if (tx == 0) {
#pragma unroll
        for (int i = 0; i < 8; i++) den_sh[ty * 8 + i] = dacc[i];
    }
    __syncthreads();

#pragma unroll
    for (int i = 0; i < 8; i++) {
        float inv = 1.0f / den_sh[ty * 8 + i];
        float4 o = make_float4(acc[i][0] * inv, acc[i][1] * inv,
                               acc[i][2] * inv, acc[i][3] * inv);
        *(float4*)(g_att + (size_t)(r0 + ty * 8 + i) * NDIM + h * ND + tx * 4) = o;
    }
}

// ---------------- launch ----------------
extern "C" void kernel_launch(void* const* d_in, const int* in_sizes, int n_in,
                              void* d_out, int out_size)
{
    const float* x        = (const float*)d_in[0];
    const float* qkv_w    = (const float*)d_in[1];
    const float* qkv_b    = (const float*)d_in[2];
    const float* proj_w   = (const float*)d_in[3];
    const float* proj_b   = (const float*)d_in[4];
    const float* proj_mat = (const float*)d_in[5];
    float* out = (float*)d_out;

    float *qkv_p, *kv_p, *att_p;
    cudaGetSymbolAddress((void**)&qkv_p, g_qkv);
    cudaGetSymbolAddress((void**)&kv_p,  g_kv);
    cudaGetSymbolAddress((void**)&att_p, g_att);

    // K0: zero kv accumulator
    const int kvn = NB * NH * NM * KV_N;
    zero_kernel<<<(kvn + 255) / 256, 256>>>(kv_p, kvn);

    // K1: qkv = x @ qkv_w^T + qkv_b          [32768 x 2304 x 768]
    sgemm_nt_bias<<<dim3((3 * NDIM) / 128, NTOK / 128), 256>>>(
        x, qkv_w, qkv_b, qkv_p, 3 * NDIM, NDIM);

    // K2: q_p, k_p = relu(ratio * {q,k} @ pm^T) + eps   [393216 x 256 x 64] x2
    feature_kernel<<<dim3(NM / 128, NRH / 128, 2), 256>>>(proj_mat);

    // K3: kv_ext = k_p^T @ [v | 1] per (b,h)
    kv_kernel<<<dim3(NB * NH, NL / 512), 256>>>();

    // K4: att = (q_p @ kv) / (q_p @ k_sum)
    attn_out_kernel<<<dim3(NL / 128, NH, NB), 256>>>();

    // K5: out = att @ proj_w^T + proj_b      [32768 x 768 x 768]
    sgemm_nt_bias<<<dim3(NDIM / 128, NTOK / 128), 256>>>(
        att_p, proj_w, proj_b, out, NDIM, NDIM);
}

// round 5
// speedup vs baseline: 1.4253x; 1.4253x over previous
#include <cuda_runtime.h>
#include <cuda_bf16.h>
#include <cstdint>

// ---------------- problem constants ----------------
#define NB   8
#define NL   4096
#define NDIM 768
#define NH   12
#define ND   64
#define NM   256
#define NTOK (NB * NL)     // 32768
#define NRH  (NTOK * NH)   // 393216
#define KV_N 65
#define FEPS 1.0e-3f
#define RATIO 0.0625f

// ---------------- scratch (static device globals; no allocs) ----------------
__device__ __align__(128) float g_qkv[(size_t)NTOK * 3 * NDIM];     // 302 MB
__device__ __align__(128) float g_qp [(size_t)NRH * NM];            // 402 MB [b,h,l,m]
__device__ __align__(128) float g_kp [(size_t)NRH * NM];            // 402 MB [b,h,l,m]
__device__ __align__(128) float g_kv [(size_t)NB * NH * NM * KV_N]; // 6.4 MB
__device__ __align__(128) float g_att[(size_t)NTOK * NDIM];         // 100 MB

// bf16 hi|lo split buffers
__device__ __align__(128) __nv_bfloat16 g_xs [(size_t)NTOK * 1536];  // x      [r][hi768|lo768]
__device__ __align__(128) __nv_bfloat16 g_ws [(size_t)2304 * 1536];  // qkv_w
__device__ __align__(128) __nv_bfloat16 g_pws[(size_t)768  * 1536];  // proj_w
__device__ __align__(128) __nv_bfloat16 g_pms[(size_t)256  * 128];   // proj_mat [m][hi64|lo64]
__device__ __align__(128) __nv_bfloat16 g_qks[(size_t)2 * NRH * 128];// q|k [b,h,l][hi64|lo64]
__device__ __align__(128) __nv_bfloat16 g_as [(size_t)NTOK * 1536];  // att

// ---------------- PTX helpers ----------------
__device__ __forceinline__ uint32_t s2u(const void* p) {
    uint32_t a;
    asm("{ .reg .u64 t; cvta.to.shared.u64 t, %1; cvt.u32.u64 %0, t; }" : "=r"(a) : "l"(p));
    return a;
}
__device__ __forceinline__ void cpa16(uint32_t s, const void* g) {
    asm volatile("cp.async.cg.shared.global [%0], [%1], 16;\n" :: "r"(s), "l"(g));
}
#define CP_COMMIT() asm volatile("cp.async.commit_group;\n" ::: "memory")
#define CP_WAIT(n)  asm volatile("cp.async.wait_group %0;\n" :: "n"(n) : "memory")
#define SW128(o) ((o) ^ (((o) >> 3) & 0x70))

__device__ __forceinline__ void ldsm_x4(uint32_t* r, uint32_t addr) {
    asm volatile("ldmatrix.sync.aligned.m8n8.x4.shared.b16 {%0,%1,%2,%3}, [%4];"
                 : "=r"(r[0]), "=r"(r[1]), "=r"(r[2]), "=r"(r[3]) : "r"(addr));
}
__device__ __forceinline__ void mma16816(float* d, const uint32_t* a, uint32_t b0, uint32_t b1) {
    asm volatile(
        "mma.sync.aligned.m16n8k16.row.col.f32.bf16.bf16.f32 "
        "{%0,%1,%2,%3}, {%4,%5,%6,%7}, {%8,%9}, {%0,%1,%2,%3};"
        : "+f"(d[0]), "+f"(d[1]), "+f"(d[2]), "+f"(d[3])
        : "r"(a[0]), "r"(a[1]), "r"(a[2]), "r"(a[3]), "r"(b0), "r"(b1));
}

// ---------------- K0: zero ----------------
__global__ void zero_kernel(float* __restrict__ p, int n) {
    int i = blockIdx.x * blockDim.x + threadIdx.x;
    if (i < n) p[i] = 0.0f;
}

// ---------------- fp32 -> bf16 hi|lo row split ----------------
__global__ void split_kernel(const float* __restrict__ src, __nv_bfloat16* __restrict__ dst, int k) {
    int c = blockIdx.y * 256 + threadIdx.x;
    if (c >= k) return;
    size_t r = blockIdx.x;
    float v = src[r * k + c];
    __nv_bfloat16 hi = __float2bfloat16(v);
    float lo = v - __bfloat162float(hi);
    dst[r * (size_t)(2 * k) + c]     = hi;
    dst[r * (size_t)(2 * k) + k + c] = __float2bfloat16(lo);
}

// ---------------- q/k gather+split into [b,h,l][hi64|lo64] ----------------
__global__ void qksplit_kernel() {
    const int sel = blockIdx.z;   // 0=q, 1=k
    size_t idx = (size_t)blockIdx.x * 256 + threadIdx.x;   // < NRH*64
    int d = (int)(idx & 63);
    size_t rest = idx >> 6;       // bh*NL + l
    int l  = (int)(rest & (NL - 1));
    int bh = (int)(rest >> 12);
    int b = bh / NH, h = bh - b * NH;
    float v = g_qkv[(size_t)(b * NL + l) * (3 * NDIM) + sel * NDIM + h * ND + d];
    __nv_bfloat16 hi = __float2bfloat16(v);
    float lo = v - __bfloat162float(hi);
    __nv_bfloat16* dst = g_qks + (size_t)sel * NRH * 128 + rest * 128;
    dst[d]      = hi;
    dst[64 + d] = __float2bfloat16(lo);
}

// ---------------- bf16 split GEMM via mma.sync (HMMA) ----------------
// C[M,N] = A·B^T fp32-equivalent via 3-term bf16 split.
// A physical [rows][2*kdim] = [hi|lo]; B same. 3*kdim/64 K-chunks:
//   term t: (A part, B part) = t0:(hi,hi) t1:(lo,hi) t2:(hi,lo)
// Tile BM=128, BN=128, BK=64 bf16. 256 threads = 8 warps (4m x 2n),
// warp tile 32x64. 4-stage cp.async pipeline, SW128 smem, ldmatrix.
// mode 0: out = acc + bias[n];  mode 1: out = max(acc*RATIO,0)+FEPS.
__global__ __launch_bounds__(256, 1) void mma_gemm(
    const __nv_bfloat16* __restrict__ A, int lda,
    const __nv_bfloat16* __restrict__ B, int ldb,
    float* __restrict__ C, int ldc,
    const float* __restrict__ bias,
    int kdim, int mode)
{
    extern __shared__ char dynsm[];
    const uint32_t sbase = (s2u(dynsm) + 1023u) & ~1023u;
    const int tid = threadIdx.x;
    const int wid = tid >> 5, lid = tid & 31;
    const int wm = wid & 3, wn = wid >> 2;
    const int n0 = blockIdx.x * 128;
    const int m0 = blockIdx.y * 128;
    const int cpt = kdim >> 6;
    const int NC = 3 * cpt;

    float acc[2][8][4];
#pragma unroll
    for (int i = 0; i < 2; i++)
#pragma unroll
        for (int j = 0; j < 8; j++)
#pragma unroll
            for (int q = 0; q < 4; q++) acc[i][j][q] = 0.0f;

    auto load_chunk = [&](int c) {
        uint32_t ab = sbase + (uint32_t)(c & 3) * 32768u;
        uint32_t bb = ab + 16384u;
        int t = c / cpt, rr = c - t * cpt;
        const __nv_bfloat16* ap = A + (size_t)m0 * lda + ((t == 1) ? kdim : 0) + rr * 64;
        const __nv_bfloat16* bp = B + (size_t)n0 * ldb + ((t == 2) ? kdim : 0) + rr * 64;
#pragma unroll
        for (int i = 0; i < 4; i++) {
            int idx = tid + (i << 8);
            int row = idx >> 3, ch = idx & 7;
            cpa16(ab + SW128(row * 128 + ch * 16), ap + (size_t)row * lda + ch * 8);
        }
#pragma unroll
        for (int i = 0; i < 4; i++) {
            int idx = tid + (i << 8);
            int row = idx >> 3, ch = idx & 7;
            cpa16(bb + SW128(row * 128 + ch * 16), bp + (size_t)row * ldb + ch * 8);
        }
    };

    // preload up to 3 stages; ALWAYS commit (empty groups keep the count exact)
#pragma unroll
    for (int i = 0; i < 3; i++) {
        if (i < NC) load_chunk(i);
        CP_COMMIT();
    }

    // ldmatrix lane geometry (rows fixed per lane; k-chunk varies)
    const int lt = lid >> 3;            // tile index 0..3 within x4
    const int lr = lid & 7;             // row within 8x8 tile
    const int rowa0 = wm * 32 + ((lt & 1) << 3) + lr;    // + mi*16
    const int cka   = lt >> 1;                           // k-chunk lsb for A
    const int rowb0 = wn * 64 + ((lt >> 1) << 3) + lr;   // + ng*16
    const int ckb   = lt & 1;                            // k-chunk lsb for B

    for (int c = 0; c < NC; c++) {
        CP_WAIT(2);
        __syncthreads();
        if (c + 3 < NC) load_chunk(c + 3);
        CP_COMMIT();

        uint32_t ab = sbase + (uint32_t)(c & 3) * 32768u;
        uint32_t bb = ab + 16384u;
#pragma unroll
        for (int ks = 0; ks < 4; ks++) {
            uint32_t afr[2][4];
#pragma unroll
            for (int mi = 0; mi < 2; mi++) {
                int row = rowa0 + mi * 16;
                int off = row * 128 + (ks * 2 + cka) * 16;
                ldsm_x4(afr[mi], ab + SW128(off));
            }
            uint32_t bfr[4][4];
#pragma unroll
            for (int ng = 0; ng < 4; ng++) {
                int row = rowb0 + ng * 16;
                int off = row * 128 + (ks * 2 + ckb) * 16;
                ldsm_x4(bfr[ng], bb + SW128(off));
            }
#pragma unroll
            for (int mi = 0; mi < 2; mi++)
#pragma unroll
                for (int ni = 0; ni < 8; ni++)
                    mma16816(acc[mi][ni], afr[mi],
                             bfr[ni >> 1][(ni & 1) * 2], bfr[ni >> 1][(ni & 1) * 2 + 1]);
        }
        __syncthreads();
    }

    // epilogue
    const int rbase = m0 + wm * 32 + (lid >> 2);
    const int cbase = n0 + wn * 64 + (lid & 3) * 2;
#pragma unroll
    for (int mi = 0; mi < 2; mi++) {
#pragma unroll
        for (int ni = 0; ni < 8; ni++) {
            int col = cbase + ni * 8;
            float b0 = 0.0f, b1 = 0.0f;
            if (mode == 0) { b0 = bias[col]; b1 = bias[col + 1]; }
            float v0 = acc[mi][ni][0], v1 = acc[mi][ni][1];
            float v2 = acc[mi][ni][2], v3 = acc[mi][ni][3];
            if (mode == 0) { v0 += b0; v1 += b1; v2 += b0; v3 += b1; }
            else {
                v0 = fmaxf(v0 * RATIO, 0.0f) + FEPS;
                v1 = fmaxf(v1 * RATIO, 0.0f) + FEPS;
                v2 = fmaxf(v2 * RATIO, 0.0f) + FEPS;
                v3 = fmaxf(v3 * RATIO, 0.0f) + FEPS;
            }
            int r0 = rbase + mi * 16;
            *(float2*)(C + (size_t)r0 * ldc + col)       = make_float2(v0, v1);
            *(float2*)(C + (size_t)(r0 + 8) * ldc + col) = make_float2(v2, v3);
        }
    }
}

// ---------------- K3: kv_ext[b,h] = k_p^T @ [v | 1], atomic accumulate ----------------
__global__ __launch_bounds__(512) void kv_kernel() {
    const int bh = blockIdx.x;
    const int b = bh / NH, h = bh - b * NH;
    const int l0 = blockIdx.y * 256;
    const int m = threadIdx.x >> 1;
    const int half = threadIdx.x & 1;

    __shared__ float  kp_sh[8][256];
    __shared__ float4 v_sh[8][16];

    float acc[33];
#pragma unroll
    for (int i = 0; i < 33; i++) acc[i] = 0.0f;

    const float* kpb = g_kp + ((size_t)bh * NL + l0) * NM;
    const size_t vbase = (size_t)(b * NL + l0) * (3 * NDIM) + 2 * NDIM + h * ND;

    for (int li = 0; li < 256; li += 8) {
        {
            int idx = threadIdx.x;
            int r = idx >> 6, cg = idx & 63;
            *(float4*)&kp_sh[r][cg * 4] = *(const float4*)(kpb + (size_t)(li + r) * NM + cg * 4);
        }
        if (threadIdx.x < 128) {
            int r = threadIdx.x >> 4, dg = threadIdx.x & 15;
            v_sh[r][dg] = *(const float4*)(g_qkv + vbase + (size_t)(li + r) * (3 * NDIM) + dg * 4);
        }
        __syncthreads();
#pragma unroll
        for (int jj = 0; jj < 8; jj++) {
            float kp = kp_sh[jj][m];
#pragma unroll
            for (int q = 0; q < 8; q++) {
                float4 v4 = v_sh[jj][half * 8 + q];
                acc[q*4+0] += kp * v4.x;
                acc[q*4+1] += kp * v4.y;
                acc[q*4+2] += kp * v4.z;
                acc[q*4+3] += kp * v4.w;
            }
            acc[32] += kp;
        }
        __syncthreads();
    }

    float* op = g_kv + ((size_t)bh * NM + m) * KV_N;
#pragma unroll
    for (int i = 0; i < 32; i++) atomicAdd(&op[half * 32 + i], acc[i]);
    if (half) atomicAdd(&op[64], acc[32]);
}

// ---------------- K4: att = (q_p @ kv) / (q_p @ k_sum) ----------------
__global__ __launch_bounds__(256) void attn_out_kernel() {
    const int b = blockIdx.z, h = blockIdx.y;
    const int bh = b * NH + h;
    const size_t qrow0 = (size_t)bh * NL + blockIdx.x * 128;
    const int tok0 = b * NL + blockIdx.x * 128;
    const int tid = threadIdx.x;
    const int tx = tid & 15, ty = tid >> 4;

    __shared__ float q_sh[32][132];
    __shared__ float kv_sh[32][68];
    __shared__ float den_sh[128];

    float acc[8][4];
    float dacc[8];
#pragma unroll
    for (int i = 0; i < 8; i++) {
        dacc[i] = 0.0f;
#pragma unroll
        for (int j = 0; j < 4; j++) acc[i][j] = 0.0f;
    }

    const float* kvb = g_kv + (size_t)bh * NM * KV_N;

    for (int k0 = 0; k0 < NM; k0 += 32) {
        for (int idx = tid; idx < 32 * KV_N; idx += 256) {
            int k = idx / KV_N, n = idx - k * KV_N;
            kv_sh[k][n] = kvb[(size_t)(k0 + k) * KV_N + n];
        }
#pragma unroll
        for (int it = 0; it < 4; it++) {
            int lin = tid + it * 256;
            int row = lin >> 3;
            int kg  = (lin & 7) << 2;
            float4 v = *(const float4*)(g_qp + (qrow0 + row) * NM + k0 + kg);
            q_sh[kg+0][row] = v.x; q_sh[kg+1][row] = v.y;
            q_sh[kg+2][row] = v.z; q_sh[kg+3][row] = v.w;
        }
        __syncthreads();
#pragma unroll
        for (int k = 0; k < 32; k++) {
            float a[8];
            *(float4*)&a[0] = *(const float4*)&q_sh[k][ty * 8];
            *(float4*)&a[4] = *(const float4*)&q_sh[k][ty * 8 + 4];
            float4 bv = *(const float4*)&kv_sh[k][tx * 4];
#pragma unroll
            for (int i = 0; i < 8; i++) {
                acc[i][0] += a[i] * bv.x;
                acc[i][1] += a[i] * bv.y;
                acc[i][2] += a[i] * bv.z;
                acc[i][3] += a[i] * bv.w;
            }
            if (tx == 0) {
                float ks = kv_sh[k][64];
#pragma unroll
                for (int i = 0; i < 8; i++) dacc[i] += a[i] * ks;
            }
        }
        __syncthreads();
    }

    if (tx == 0) {
#pragma unroll
        for (int i = 0; i < 8; i++) den_sh[ty * 8 + i] = dacc[i];
    }
    __syncthreads();

#pragma unroll
    for (int i = 0; i < 8; i++) {
        float inv = 1.0f / den_sh[ty * 8 + i];
        float4 o = make_float4(acc[i][0] * inv, acc[i][1] * inv,
                               acc[i][2] * inv, acc[i][3] * inv);
        *(float4*)(g_att + (size_t)(tok0 + ty * 8 + i) * NDIM + h * ND + tx * 4) = o;
    }
}

// ---------------- launch ----------------
extern "C" void kernel_launch(void* const* d_in, const int* in_sizes, int n_in,
                              void* d_out, int out_size)
{
    const float* x        = (const float*)d_in[0];
    const float* qkv_w    = (const float*)d_in[1];
    const float* qkv_b    = (const float*)d_in[2];
    const float* proj_w   = (const float*)d_in[3];
    const float* proj_b   = (const float*)d_in[4];
    const float* proj_mat = (const float*)d_in[5];
    float* out = (float*)d_out;

    float *qkv_p, *qp_p, *kp_p, *kv_p, *att_p;
    __nv_bfloat16 *xs_p, *ws_p, *pws_p, *pms_p, *qks_p, *as_p;
    cudaGetSymbolAddress((void**)&qkv_p, g_qkv);
    cudaGetSymbolAddress((void**)&qp_p,  g_qp);
    cudaGetSymbolAddress((void**)&kp_p,  g_kp);
    cudaGetSymbolAddress((void**)&kv_p,  g_kv);
    cudaGetSymbolAddress((void**)&att_p, g_att);
    cudaGetSymbolAddress((void**)&xs_p,  g_xs);
    cudaGetSymbolAddress((void**)&ws_p,  g_ws);
    cudaGetSymbolAddress((void**)&pws_p, g_pws);
    cudaGetSymbolAddress((void**)&pms_p, g_pms);
    cudaGetSymbolAddress((void**)&qks_p, g_qks);
    cudaGetSymbolAddress((void**)&as_p,  g_as);

    const int SMEM_GEMM = 4 * 32768 + 1024;   // 4-stage double tiles + align pad
    cudaFuncSetAttribute(mma_gemm, cudaFuncAttributeMaxDynamicSharedMemorySize, SMEM_GEMM);

    // zero kv accumulator
    const int kvn = NB * NH * NM * KV_N;
    zero_kernel<<<(kvn + 255) / 256, 256>>>(kv_p, kvn);

    // splits of inputs
    split_kernel<<<dim3(NTOK, 3), 256>>>(x,        xs_p,  768);
    split_kernel<<<dim3(2304, 3), 256>>>(qkv_w,    ws_p,  768);
    split_kernel<<<dim3(768,  3), 256>>>(proj_w,   pws_p, 768);
    split_kernel<<<dim3(256,  1), 256>>>(proj_mat, pms_p, 64);

    // K1: qkv = x @ qkv_w^T + b      [32768 x 2304 x 768]
    mma_gemm<<<dim3(2304 / 128, NTOK / 128), 256, SMEM_GEMM>>>(
        xs_p, 1536, ws_p, 1536, qkv_p, 3 * NDIM, qkv_b, 768, 0);

    // gather+split q,k into [b,h,l][hi|lo]
    qksplit_kernel<<<dim3((NRH * ND) / 256, 1, 2), 256>>>();

    // K2: q_p / k_p = relu(ratio * {q,k} @ pm^T) + eps   [393216 x 256 x 64]
    mma_gemm<<<dim3(NM / 128, NRH / 128), 256, SMEM_GEMM>>>(
        qks_p, 128, pms_p, 128, qp_p, NM, qkv_b, 64, 1);
    mma_gemm<<<dim3(NM / 128, NRH / 128), 256, SMEM_GEMM>>>(
        qks_p + (size_t)NRH * 128, 128, pms_p, 128, kp_p, NM, qkv_b, 64, 1);

    // K3: kv_ext = k_p^T @ [v | 1]
    kv_kernel<<<dim3(NB * NH, NL / 256), 512>>>();

    // K4: att = (q_p @ kv) / den
    attn_out_kernel<<<dim3(NL / 128, NH, NB), 256>>>();

    // split att
    split_kernel<<<dim3(NTOK, 3), 256>>>(att_p, as_p, 768);

    // K5: out = att @ proj_w^T + proj_b    [32768 x 768 x 768]
    mma_gemm<<<dim3(NDIM / 128, NTOK / 128), 256, SMEM_GEMM>>>(
        as_p, 1536, pws_p, 1536, out, NDIM, proj_b, 768, 0);
}

// round 6
// speedup vs baseline: 1.6771x; 1.1767x over previous
#include <cuda_runtime.h>
#include <cuda_bf16.h>
#include <cstdint>

// ---------------- problem constants ----------------
#define NB   8
#define NL   4096
#define NDIM 768
#define NH   12
#define ND   64
#define NM   256
#define NTOK (NB * NL)     // 32768
#define NRH  (NTOK * NH)   // 393216
#define KV_N 65
#define FEPS 1.0e-3f
#define RATIO 0.0625f

// ---------------- scratch (static device globals; no allocs) ----------------
__device__ __align__(128) float g_v  [(size_t)NTOK * NDIM];         // 100 MB  v, [token][768]
__device__ __align__(128) float g_qp [(size_t)NRH * NM];            // 402 MB [b,h,l,m]
__device__ __align__(128) float g_kp [(size_t)NRH * NM];            // 402 MB [b,h,l,m]
__device__ __align__(128) float g_kv [(size_t)NB * NH * NM * KV_N]; // 6.4 MB

__device__ __align__(128) __nv_bfloat16 g_xs [(size_t)NTOK * 1536];  // x split [r][hi768|lo768]
__device__ __align__(128) __nv_bfloat16 g_ws [(size_t)2304 * 1536];  // qkv_w split
__device__ __align__(128) __nv_bfloat16 g_pws[(size_t)768  * 1536];  // proj_w split
__device__ __align__(128) __nv_bfloat16 g_pms[(size_t)256  * 128];   // proj_mat split [m][hi64|lo64]
__device__ __align__(128) __nv_bfloat16 g_qks[(size_t)2 * NRH * 128];// q|k split [sel][b,h,l][hi64|lo64]
__device__ __align__(128) __nv_bfloat16 g_as [(size_t)NTOK * 1536];  // att split [r][hi768|lo768]

// ---------------- PTX helpers ----------------
__device__ __forceinline__ uint32_t s2u(const void* p) {
    uint32_t a;
    asm("{ .reg .u64 t; cvta.to.shared.u64 t, %1; cvt.u32.u64 %0, t; }" : "=r"(a) : "l"(p));
    return a;
}
__device__ __forceinline__ void cpa16(uint32_t s, const void* g) {
    asm volatile("cp.async.cg.shared.global [%0], [%1], 16;\n" :: "r"(s), "l"(g));
}
#define CP_COMMIT() asm volatile("cp.async.commit_group;\n" ::: "memory")
#define CP_WAIT(n)  asm volatile("cp.async.wait_group %0;\n" :: "n"(n) : "memory")
#define SW128(o) ((o) ^ (((o) >> 3) & 0x70))

__device__ __forceinline__ void ldsm_x4(uint32_t* r, uint32_t addr) {
    asm volatile("ldmatrix.sync.aligned.m8n8.x4.shared.b16 {%0,%1,%2,%3}, [%4];"
                 : "=r"(r[0]), "=r"(r[1]), "=r"(r[2]), "=r"(r[3]) : "r"(addr));
}
__device__ __forceinline__ void mma16816(float* d, const uint32_t* a, uint32_t b0, uint32_t b1) {
    asm volatile(
        "mma.sync.aligned.m16n8k16.row.col.f32.bf16.bf16.f32 "
        "{%0,%1,%2,%3}, {%4,%5,%6,%7}, {%8,%9}, {%0,%1,%2,%3};"
        : "+f"(d[0]), "+f"(d[1]), "+f"(d[2]), "+f"(d[3])
        : "r"(a[0]), "r"(a[1]), "r"(a[2]), "r"(a[3]), "r"(b0), "r"(b1));
}
__device__ __forceinline__ uint32_t pack2(float v0, float v1) {
    return (uint32_t)__bfloat16_as_ushort(__float2bfloat16(v0)) |
           ((uint32_t)__bfloat16_as_ushort(__float2bfloat16(v1)) << 16);
}

// ---------------- K0: zero ----------------
__global__ void zero_kernel(float* __restrict__ p, int n) {
    int i = blockIdx.x * blockDim.x + threadIdx.x;
    if (i < n) p[i] = 0.0f;
}

// ---------------- fp32 -> bf16 hi|lo row split (vectorized grid-stride) ----------------
__global__ void split4_kernel(const float* __restrict__ src, __nv_bfloat16* __restrict__ dst,
                              int k, int total /* rows*k/4 */) {
    for (int i = blockIdx.x * blockDim.x + threadIdx.x; i < total; i += gridDim.x * blockDim.x) {
        int e = i * 4;
        int r = e / k, c = e - r * k;
        float4 v = *(const float4*)(src + (size_t)r * k + c);
        __nv_bfloat16 h0 = __float2bfloat16(v.x), h1 = __float2bfloat16(v.y);
        __nv_bfloat16 h2 = __float2bfloat16(v.z), h3 = __float2bfloat16(v.w);
        uint2 hi, lo;
        hi.x = (uint32_t)__bfloat16_as_ushort(h0) | ((uint32_t)__bfloat16_as_ushort(h1) << 16);
        hi.y = (uint32_t)__bfloat16_as_ushort(h2) | ((uint32_t)__bfloat16_as_ushort(h3) << 16);
        lo.x = pack2(v.x - __bfloat162float(h0), v.y - __bfloat162float(h1));
        lo.y = pack2(v.z - __bfloat162float(h2), v.w - __bfloat162float(h3));
        *(uint2*)(dst + (size_t)r * 2 * k + c)     = hi;
        *(uint2*)(dst + (size_t)r * 2 * k + k + c) = lo;
    }
}

// ---------------- bf16 split GEMM via mma.sync (HMMA) ----------------
// C = A·B^T fp32-equivalent via 3-term bf16 split (hi·hi + lo·hi + hi·lo).
// A physical [rows][2*kdim]=[hi|lo]; B same. Tile BM=BN=128, BK=64 bf16.
// 256 threads = 8 warps (4m x 2n), warp tile 32x64. 3-stage cp.async, SW128, ldmatrix.
// mode 0: C += bias.  mode 1: C = relu(acc*RATIO)+FEPS.
// mode 2: qkv epilogue — q,k as split bf16 -> g_qks; v fp32 -> g_v.
__global__ __launch_bounds__(256, 2) void mma_gemm(
    const __nv_bfloat16* __restrict__ A, int lda,
    const __nv_bfloat16* __restrict__ B, int ldb,
    float* __restrict__ C, int ldc,
    const float* __restrict__ bias,
    int kdim, int mode)
{
    extern __shared__ char dynsm[];
    const uint32_t sbase = (s2u(dynsm) + 1023u) & ~1023u;
    const int tid = threadIdx.x;
    const int wid = tid >> 5, lid = tid & 31;
    const int wm = wid & 3, wn = wid >> 2;
    const int n0 = blockIdx.x * 128;
    const int m0 = blockIdx.y * 128;
    const int cpt = kdim >> 6;
    const int NC = 3 * cpt;

    float acc[2][8][4];
#pragma unroll
    for (int i = 0; i < 2; i++)
#pragma unroll
        for (int j = 0; j < 8; j++)
#pragma unroll
            for (int q = 0; q < 4; q++) acc[i][j][q] = 0.0f;

    auto load_chunk = [&](int c) {
        int slot = c % 3;
        uint32_t ab = sbase + (uint32_t)slot * 32768u;
        uint32_t bb = ab + 16384u;
        int t = c / cpt, rr = c - t * cpt;
        const __nv_bfloat16* ap = A + (size_t)m0 * lda + ((t == 1) ? kdim : 0) + rr * 64;
        const __nv_bfloat16* bp = B + (size_t)n0 * ldb + ((t == 2) ? kdim : 0) + rr * 64;
#pragma unroll
        for (int i = 0; i < 4; i++) {
            int idx = tid + (i << 8);
            int row = idx >> 3, ch = idx & 7;
            cpa16(ab + SW128(row * 128 + ch * 16), ap + (size_t)row * lda + ch * 8);
        }
#pragma unroll
        for (int i = 0; i < 4; i++) {
            int idx = tid + (i << 8);
            int row = idx >> 3, ch = idx & 7;
            cpa16(bb + SW128(row * 128 + ch * 16), bp + (size_t)row * ldb + ch * 8);
        }
    };

#pragma unroll
    for (int i = 0; i < 3; i++) {
        if (i < NC) load_chunk(i);
        CP_COMMIT();
    }

    const int lt = lid >> 3;
    const int lr = lid & 7;
    const int rowa0 = wm * 32 + ((lt & 1) << 3) + lr;
    const int cka   = lt >> 1;
    const int rowb0 = wn * 64 + ((lt >> 1) << 3) + lr;
    const int ckb   = lt & 1;

    for (int c = 0; c < NC; c++) {
        CP_WAIT(2);
        __syncthreads();

        uint32_t ab = sbase + (uint32_t)(c % 3) * 32768u;
        uint32_t bb = ab + 16384u;
#pragma unroll
        for (int ks = 0; ks < 4; ks++) {
            uint32_t afr[2][4];
#pragma unroll
            for (int mi = 0; mi < 2; mi++) {
                int row = rowa0 + mi * 16;
                int off = row * 128 + (ks * 2 + cka) * 16;
                ldsm_x4(afr[mi], ab + SW128(off));
            }
            uint32_t bfr[4][4];
#pragma unroll
            for (int ng = 0; ng < 4; ng++) {
                int row = rowb0 + ng * 16;
                int off = row * 128 + (ks * 2 + ckb) * 16;
                ldsm_x4(bfr[ng], bb + SW128(off));
            }
#pragma unroll
            for (int mi = 0; mi < 2; mi++)
#pragma unroll
                for (int ni = 0; ni < 8; ni++)
                    mma16816(acc[mi][ni], afr[mi],
                             bfr[ni >> 1][(ni & 1) * 2], bfr[ni >> 1][(ni & 1) * 2 + 1]);
        }
        __syncthreads();
        if (c + 3 < NC) load_chunk(c + 3);
        CP_COMMIT();
    }

    // ---------------- epilogue ----------------
    const int rbase = m0 + wm * 32 + (lid >> 2);
    const int d0 = (lid & 3) * 2;                  // even col offset within warp n-halve
    const int cbase = n0 + wn * 64 + d0;

    if (mode == 2) {
        const int region = n0 / 768;               // 0=q, 1=k, 2=v
        if (region < 2) {
            const int h = ((n0 % 768) >> 6) + wn;  // head for this warp column-half
#pragma unroll
            for (int mi = 0; mi < 2; mi++) {
#pragma unroll
                for (int rr = 0; rr < 2; rr++) {
                    int r = rbase + mi * 16 + rr * 8;
                    int b = r >> 12, l = r & (NL - 1);
                    __nv_bfloat16* dst = g_qks +
                        ((size_t)region * NRH + (size_t)(b * NH + h) * NL + l) * 128;
#pragma unroll
                    for (int ni = 0; ni < 8; ni++) {
                        int col = cbase + ni * 8;
                        float v0 = acc[mi][ni][rr * 2]     + bias[col];
                        float v1 = acc[mi][ni][rr * 2 + 1] + bias[col + 1];
                        __nv_bfloat16 h0 = __float2bfloat16(v0);
                        __nv_bfloat16 h1 = __float2bfloat16(v1);
                        int d = d0 + ni * 8;
                        *(uint32_t*)(dst + d) =
                            (uint32_t)__bfloat16_as_ushort(h0) |
                            ((uint32_t)__bfloat16_as_ushort(h1) << 16);
                        *(uint32_t*)(dst + 64 + d) =
                            pack2(v0 - __bfloat162float(h0), v1 - __bfloat162float(h1));
                    }
                }
            }
        } else {
#pragma unroll
            for (int mi = 0; mi < 2; mi++) {
#pragma unroll
                for (int rr = 0; rr < 2; rr++) {
                    int r = rbase + mi * 16 + rr * 8;
#pragma unroll
                    for (int ni = 0; ni < 8; ni++) {
                        int col = cbase + ni * 8;
                        float v0 = acc[mi][ni][rr * 2]     + bias[col];
                        float v1 = acc[mi][ni][rr * 2 + 1] + bias[col + 1];
                        *(float2*)(g_v + (size_t)r * NDIM + (col - 1536)) = make_float2(v0, v1);
                    }
                }
            }
        }
        return;
    }

#pragma unroll
    for (int mi = 0; mi < 2; mi++) {
#pragma unroll
        for (int ni = 0; ni < 8; ni++) {
            int col = cbase + ni * 8;
            float b0 = 0.0f, b1 = 0.0f;
            if (mode == 0) { b0 = bias[col]; b1 = bias[col + 1]; }
            float v0 = acc[mi][ni][0], v1 = acc[mi][ni][1];
            float v2 = acc[mi][ni][2], v3 = acc[mi][ni][3];
            if (mode == 0) { v0 += b0; v1 += b1; v2 += b0; v3 += b1; }
            else {
                v0 = fmaxf(v0 * RATIO, 0.0f) + FEPS;
                v1 = fmaxf(v1 * RATIO, 0.0f) + FEPS;
                v2 = fmaxf(v2 * RATIO, 0.0f) + FEPS;
                v3 = fmaxf(v3 * RATIO, 0.0f) + FEPS;
            }
            int r0 = rbase + mi * 16;
            *(float2*)(C + (size_t)r0 * ldc + col)       = make_float2(v0, v1);
            *(float2*)(C + (size_t)(r0 + 8) * ldc + col) = make_float2(v2, v3);
        }
    }
}

// ---------------- K3: kv_ext[b,h] = k_p^T @ [v | 1], atomic accumulate ----------------
__global__ __launch_bounds__(512) void kv_kernel() {
    const int bh = blockIdx.x;
    const int b = bh / NH, h = bh - b * NH;
    const int l0 = blockIdx.y * 256;
    const int m = threadIdx.x >> 1;
    const int half = threadIdx.x & 1;

    __shared__ float  kp_sh[8][256];
    __shared__ float4 v_sh[8][16];

    float acc[33];
#pragma unroll
    for (int i = 0; i < 33; i++) acc[i] = 0.0f;

    const float* kpb = g_kp + ((size_t)bh * NL + l0) * NM;
    const size_t vbase = (size_t)(b * NL + l0) * NDIM + h * ND;

    for (int li = 0; li < 256; li += 8) {
        {
            int idx = threadIdx.x;
            int r = idx >> 6, cg = idx & 63;
            *(float4*)&kp_sh[r][cg * 4] = *(const float4*)(kpb + (size_t)(li + r) * NM + cg * 4);
        }
        if (threadIdx.x < 128) {
            int r = threadIdx.x >> 4, dg = threadIdx.x & 15;
            v_sh[r][dg] = *(const float4*)(g_v + vbase + (size_t)(li + r) * NDIM + dg * 4);
        }
        __syncthreads();
#pragma unroll
        for (int jj = 0; jj < 8; jj++) {
            float kp = kp_sh[jj][m];
#pragma unroll
            for (int q = 0; q < 8; q++) {
                float4 v4 = v_sh[jj][half * 8 + q];
                acc[q*4+0] += kp * v4.x;
                acc[q*4+1] += kp * v4.y;
                acc[q*4+2] += kp * v4.z;
                acc[q*4+3] += kp * v4.w;
            }
            acc[32] += kp;
        }
        __syncthreads();
    }

    float* op = g_kv + ((size_t)bh * NM + m) * KV_N;
#pragma unroll
    for (int i = 0; i < 32; i++) atomicAdd(&op[half * 32 + i], acc[i]);
    if (half) atomicAdd(&op[64], acc[32]);
}

// ---------------- K4: att = (q_p @ kv) / (q_p @ k_sum), write split bf16 ----------------
__global__ __launch_bounds__(256) void attn_out_kernel() {
    const int b = blockIdx.z, h = blockIdx.y;
    const int bh = b * NH + h;
    const size_t qrow0 = (size_t)bh * NL + blockIdx.x * 128;
    const int tok0 = b * NL + blockIdx.x * 128;
    const int tid = threadIdx.x;
    const int tx = tid & 15, ty = tid >> 4;

    __shared__ float q_sh[32][132];
    __shared__ float kv_sh[32][68];
    __shared__ float den_sh[128];

    float acc[8][4];
    float dacc[8];
#pragma unroll
    for (int i = 0; i < 8; i++) {
        dacc[i] = 0.0f;
#pragma unroll
        for (int j = 0; j < 4; j++) acc[i][j] = 0.0f;
    }

    const float* kvb = g_kv + (size_t)bh * NM * KV_N;

    for (int k0 = 0; k0 < NM; k0 += 32) {
        for (int idx = tid; idx < 32 * KV_N; idx += 256) {
            int k = idx / KV_N, n = idx - k * KV_N;
            kv_sh[k][n] = kvb[(size_t)(k0 + k) * KV_N + n];
        }
#pragma unroll
        for (int it = 0; it < 4; it++) {
            int lin = tid + it * 256;
            int row = lin >> 3;
            int kg  = (lin & 7) << 2;
            float4 v = *(const float4*)(g_qp + (qrow0 + row) * NM + k0 + kg);
            q_sh[kg+0][row] = v.x; q_sh[kg+1][row] = v.y;
            q_sh[kg+2][row] = v.z; q_sh[kg+3][row] = v.w;
        }
        __syncthreads();
#pragma unroll
        for (int k = 0; k < 32; k++) {
            float a[8];
            *(float4*)&a[0] = *(const float4*)&q_sh[k][ty * 8];
            *(float4*)&a[4] = *(const float4*)&q_sh[k][ty * 8 + 4];
            float4 bv = *(const float4*)&kv_sh[k][tx * 4];
#pragma unroll
            for (int i = 0; i < 8; i++) {
                acc[i][0] += a[i] * bv.x;
                acc[i][1] += a[i] * bv.y;
                acc[i][2] += a[i] * bv.z;
                acc[i][3] += a[i] * bv.w;
            }
            if (tx == 0) {
                float ks = kv_sh[k][64];
#pragma unroll
                for (int i = 0; i < 8; i++) dacc[i] += a[i] * ks;
            }
        }
        __syncthreads();
    }

    if (tx == 0) {
#pragma unroll
        for (int i = 0; i < 8; i++) den_sh[ty * 8 + i] = dacc[i];
    }
    __syncthreads();

#pragma unroll
    for (int i = 0; i < 8; i++) {
        float inv = 1.0f / den_sh[ty * 8 + i];
        float o0 = acc[i][0] * inv, o1 = acc[i][1] * inv;
        float o2 = acc[i][2] * inv, o3 = acc[i][3] * inv;
        __nv_bfloat16 h0 = __float2bfloat16(o0), h1 = __float2bfloat16(o1);
        __nv_bfloat16 h2 = __float2bfloat16(o2), h3 = __float2bfloat16(o3);
        uint2 hi, lo;
        hi.x = (uint32_t)__bfloat16_as_ushort(h0) | ((uint32_t)__bfloat16_as_ushort(h1) << 16);
        hi.y = (uint32_t)__bfloat16_as_ushort(h2) | ((uint32_t)__bfloat16_as_ushort(h3) << 16);
        lo.x = pack2(o0 - __bfloat162float(h0), o1 - __bfloat162float(h1));
        lo.y = pack2(o2 - __bfloat162float(h2), o3 - __bfloat162float(h3));
        __nv_bfloat16* dst = g_as + (size_t)(tok0 + ty * 8 + i) * 1536 + h * ND + tx * 4;
        *(uint2*)dst         = hi;
        *(uint2*)(dst + 768) = lo;
    }
}

// ---------------- launch ----------------
extern "C" void kernel_launch(void* const* d_in, const int* in_sizes, int n_in,
                              void* d_out, int out_size)
{
    const float* x        = (const float*)d_in[0];
    const float* qkv_w    = (const float*)d_in[1];
    const float* qkv_b    = (const float*)d_in[2];
    const float* proj_w   = (const float*)d_in[3];
    const float* proj_b   = (const float*)d_in[4];
    const float* proj_mat = (const float*)d_in[5];
    float* out = (float*)d_out;

    float *qp_p, *kp_p, *kv_p;
    __nv_bfloat16 *xs_p, *ws_p, *pws_p, *pms_p, *qks_p, *as_p;
    cudaGetSymbolAddress((void**)&qp_p,  g_qp);
    cudaGetSymbolAddress((void**)&kp_p,  g_kp);
    cudaGetSymbolAddress((void**)&kv_p,  g_kv);
    cudaGetSymbolAddress((void**)&xs_p,  g_xs);
    cudaGetSymbolAddress((void**)&ws_p,  g_ws);
    cudaGetSymbolAddress((void**)&pws_p, g_pws);
    cudaGetSymbolAddress((void**)&pms_p, g_pms);
    cudaGetSymbolAddress((void**)&qks_p, g_qks);
    cudaGetSymbolAddress((void**)&as_p,  g_as);

    const int SMEM_GEMM = 3 * 32768 + 1024;   // 3-stage + align pad (2 CTAs/SM)
    cudaFuncSetAttribute(mma_gemm, cudaFuncAttributeMaxDynamicSharedMemorySize, SMEM_GEMM);

    // zero kv accumulator
    const int kvn = NB * NH * NM * KV_N;
    zero_kernel<<<(kvn + 255) / 256, 256>>>(kv_p, kvn);

    // input splits (vectorized)
    split4_kernel<<<8192, 256>>>(x,        xs_p,  768, NTOK * 768 / 4);
    split4_kernel<<<2048, 256>>>(qkv_w,    ws_p,  768, 2304 * 768 / 4);
    split4_kernel<<<1024, 256>>>(proj_w,   pws_p, 768, 768 * 768 / 4);
    split4_kernel<<<  64, 256>>>(proj_mat, pms_p, 64,  256 * 64 / 4);

    // K1: qkv = x @ qkv_w^T + b; epilogue scatters q,k split bf16 + v fp32
    mma_gemm<<<dim3(2304 / 128, NTOK / 128), 256, SMEM_GEMM>>>(
        xs_p, 1536, ws_p, 1536, nullptr, 0, qkv_b, 768, 2);

    // K2: q_p / k_p = relu(ratio * {q,k} @ pm^T) + eps
    mma_gemm<<<dim3(NM / 128, NRH / 128), 256, SMEM_GEMM>>>(
        qks_p, 128, pms_p, 128, qp_p, NM, qkv_b, 64, 1);
    mma_gemm<<<dim3(NM / 128, NRH / 128), 256, SMEM_GEMM>>>(
        qks_p + (size_t)NRH * 128, 128, pms_p, 128, kp_p, NM, qkv_b, 64, 1);

    // K3: kv_ext = k_p^T @ [v | 1]
    kv_kernel<<<dim3(NB * NH, NL / 256), 512>>>();

    // K4: att = (q_p @ kv) / den; writes split bf16 att directly
    attn_out_kernel<<<dim3(NL / 128, NH, NB), 256>>>();

    // K5: out = att @ proj_w^T + proj_b
    mma_gemm<<<dim3(NDIM / 128, NTOK / 128), 256, SMEM_GEMM>>>(
        as_p, 1536, pws_p, 1536, out, NDIM, proj_b, 768, 0);
}

// round 7
// speedup vs baseline: 1.8051x; 1.0764x over previous
#include <cuda_runtime.h>
#include <cuda_bf16.h>
#include <cstdint>

// ---------------- problem constants ----------------
#define NB   8
#define NL   4096
#define NDIM 768
#define NH   12
#define ND   64
#define NM   256
#define NTOK (NB * NL)     // 32768
#define NRH  (NTOK * NH)   // 393216
#define KV_N 65
#define FEPS 1.0e-3f
#define RATIO 0.0625f

// ---------------- scratch (static device globals; no allocs) ----------------
__device__ __align__(128) float g_v  [(size_t)NTOK * NDIM];         // 100 MB  v fp32 [token][768]
__device__ __align__(128) float g_kp [(size_t)NRH * NM];            // 402 MB  k_p fp32 [bh,l][256]
__device__ __align__(128) float g_kv [(size_t)NB * NH * NM * KV_N]; // 6.4 MB  kv fp32 [bh][m][65]

__device__ __align__(128) __nv_bfloat16 g_xs [(size_t)NTOK * 1536];   // x split [r][hi768|lo768]
__device__ __align__(128) __nv_bfloat16 g_ws [(size_t)2304 * 1536];   // qkv_w split
__device__ __align__(128) __nv_bfloat16 g_pws[(size_t)768  * 1536];   // proj_w split
__device__ __align__(128) __nv_bfloat16 g_pms[(size_t)256  * 128];    // proj_mat split [m][hi64|lo64]
__device__ __align__(128) __nv_bfloat16 g_qks[(size_t)2 * NRH * 128]; // q|k split [sel][bh,l][hi64|lo64]
__device__ __align__(128) __nv_bfloat16 g_qps[(size_t)NRH * 512];     // q_p split [bh,l][hi256|lo256]
__device__ __align__(128) __nv_bfloat16 g_kvT[(size_t)NB * NH * 128 * 512]; // kv^T split [bh][128][hi256|lo256]
__device__ __align__(128) __nv_bfloat16 g_as [(size_t)NTOK * 1536];   // att split [r][hi768|lo768]

// ---------------- PTX helpers ----------------
__device__ __forceinline__ uint32_t s2u(const void* p) {
    uint32_t a;
    asm("{ .reg .u64 t; cvta.to.shared.u64 t, %1; cvt.u32.u64 %0, t; }" : "=r"(a) : "l"(p));
    return a;
}
__device__ __forceinline__ void cpa16(uint32_t s, const void* g) {
    asm volatile("cp.async.cg.shared.global [%0], [%1], 16;\n" :: "r"(s), "l"(g));
}
#define CP_COMMIT() asm volatile("cp.async.commit_group;\n" ::: "memory")
#define CP_WAIT(n)  asm volatile("cp.async.wait_group %0;\n" :: "n"(n) : "memory")
#define SW128(o) ((o) ^ (((o) >> 3) & 0x70))

__device__ __forceinline__ void ldsm_x4(uint32_t* r, uint32_t addr) {
    asm volatile("ldmatrix.sync.aligned.m8n8.x4.shared.b16 {%0,%1,%2,%3}, [%4];"
                 : "=r"(r[0]), "=r"(r[1]), "=r"(r[2]), "=r"(r[3]) : "r"(addr));
}
__device__ __forceinline__ void mma16816(float* d, const uint32_t* a, uint32_t b0, uint32_t b1) {
    asm volatile(
        "mma.sync.aligned.m16n8k16.row.col.f32.bf16.bf16.f32 "
        "{%0,%1,%2,%3}, {%4,%5,%6,%7}, {%8,%9}, {%0,%1,%2,%3};"
        : "+f"(d[0]), "+f"(d[1]), "+f"(d[2]), "+f"(d[3])
        : "r"(a[0]), "r"(a[1]), "r"(a[2]), "r"(a[3]), "r"(b0), "r"(b1));
}
__device__ __forceinline__ uint32_t pack2(float v0, float v1) {
    return (uint32_t)__bfloat16_as_ushort(__float2bfloat16(v0)) |
           ((uint32_t)__bfloat16_as_ushort(__float2bfloat16(v1)) << 16);
}
__device__ __forceinline__ void split_pair(float v0, float v1, uint32_t& hi, uint32_t& lo) {
    __nv_bfloat16 h0 = __float2bfloat16(v0), h1 = __float2bfloat16(v1);
    hi = (uint32_t)__bfloat16_as_ushort(h0) | ((uint32_t)__bfloat16_as_ushort(h1) << 16);
    lo = pack2(v0 - __bfloat162float(h0), v1 - __bfloat162float(h1));
}

// ---------------- K0: zero ----------------
__global__ void zero_kernel(float* __restrict__ p, int n) {
    int i = blockIdx.x * blockDim.x + threadIdx.x;
    if (i < n) p[i] = 0.0f;
}

// ---------------- fp32 -> bf16 hi|lo row split ----------------
__global__ void split4_kernel(const float* __restrict__ src, __nv_bfloat16* __restrict__ dst,
                              int k, int total) {
    for (int i = blockIdx.x * blockDim.x + threadIdx.x; i < total; i += gridDim.x * blockDim.x) {
        int e = i * 4;
        int r = e / k, c = e - r * k;
        float4 v = *(const float4*)(src + (size_t)r * k + c);
        uint32_t h0, l0, h1, l1;
        split_pair(v.x, v.y, h0, l0);
        split_pair(v.z, v.w, h1, l1);
        *(uint2*)(dst + (size_t)r * 2 * k + c)     = make_uint2(h0, h1);
        *(uint2*)(dst + (size_t)r * 2 * k + k + c) = make_uint2(l0, l1);
    }
}

// ---------------- kv -> kvT split bf16, padded to 128 rows ----------------
__global__ void kvt_kernel() {
    const int bh = blockIdx.x;
    const float* src = g_kv + (size_t)bh * NM * KV_N;
    __nv_bfloat16* dst = g_kvT + (size_t)bh * 128 * 512;
    for (int i = threadIdx.x; i < 128 * 128; i += 256) {
        int n = i >> 7;
        int m2 = (i & 127) * 2;
        float v0 = 0.0f, v1 = 0.0f;
        if (n < KV_N) {
            v0 = src[(size_t)m2 * KV_N + n];
            v1 = src[(size_t)(m2 + 1) * KV_N + n];
        }
        uint32_t hi, lo;
        split_pair(v0, v1, hi, lo);
        *(uint32_t*)(dst + (size_t)n * 512 + m2)       = hi;
        *(uint32_t*)(dst + (size_t)n * 512 + 256 + m2) = lo;
    }
}

// ---------------- bf16 split GEMM via mma.sync (HMMA) ----------------
// C = A·B^T fp32-equivalent via 3-term bf16 split (hi·hi + lo·hi + hi·lo).
// Tile BM=BN=128, BK=64. 128 threads = 4 warps (2m x 2n), warp tile 64x64.
// 3-stage cp.async, SW128 smem, ldmatrix.
// MODE 0: C=acc+bias fp32 [K5]; 1: relu fp32 [K2-k]; 2: qkv scatter [K1];
// MODE 3: attn div -> g_as split [K4]; 4: relu -> g_qps split [K2-q].
template <int MODE>
__global__ __launch_bounds__(128, 2) void mma_gemm(
    const __nv_bfloat16* __restrict__ A, int lda, size_t aZ,
    const __nv_bfloat16* __restrict__ B, int ldb, size_t bZ,
    float* __restrict__ C, int ldc,
    const float* __restrict__ bias,
    int kdim)
{
    extern __shared__ char dynsm[];
    __shared__ float den_sh[128];
    const uint32_t sbase = (s2u(dynsm) + 1023u) & ~1023u;
    const int tid = threadIdx.x;
    const int wid = tid >> 5, lid = tid & 31;
    const int wm = wid & 1, wn = wid >> 1;
    const int n0 = blockIdx.x * 128;
    const int m0 = blockIdx.y * 128;
    A += (size_t)blockIdx.z * aZ;
    B += (size_t)blockIdx.z * bZ;
    const int cpt = kdim >> 6;
    const int NC = 3 * cpt;

    float acc[4][8][4];
#pragma unroll
    for (int i = 0; i < 4; i++)
#pragma unroll
        for (int j = 0; j < 8; j++)
#pragma unroll
            for (int q = 0; q < 4; q++) acc[i][j][q] = 0.0f;

    auto load_chunk = [&](int c) {
        int slot = c % 3;
        uint32_t ab = sbase + (uint32_t)slot * 32768u;
        uint32_t bb = ab + 16384u;
        int t = c / cpt, rr = c - t * cpt;
        const __nv_bfloat16* ap = A + (size_t)m0 * lda + ((t == 1) ? kdim : 0) + rr * 64;
        const __nv_bfloat16* bp = B + (size_t)n0 * ldb + ((t == 2) ? kdim : 0) + rr * 64;
#pragma unroll
        for (int i = 0; i < 8; i++) {
            int idx = tid + (i << 7);
            int row = idx >> 3, ch = idx & 7;
            cpa16(ab + SW128(row * 128 + ch * 16), ap + (size_t)row * lda + ch * 8);
        }
#pragma unroll
        for (int i = 0; i < 8; i++) {
            int idx = tid + (i << 7);
            int row = idx >> 3, ch = idx & 7;
            cpa16(bb + SW128(row * 128 + ch * 16), bp + (size_t)row * ldb + ch * 8);
        }
    };

#pragma unroll
    for (int i = 0; i < 3; i++) {
        if (i < NC) load_chunk(i);
        CP_COMMIT();
    }

    const int lt = lid >> 3;
    const int lr = lid & 7;
    const int rowa0 = wm * 64 + ((lt & 1) << 3) + lr;
    const int cka   = lt >> 1;
    const int rowb0 = wn * 64 + ((lt >> 1) << 3) + lr;
    const int ckb   = lt & 1;

    for (int c = 0; c < NC; c++) {
        CP_WAIT(2);
        __syncthreads();

        uint32_t ab = sbase + (uint32_t)(c % 3) * 32768u;
        uint32_t bb = ab + 16384u;
#pragma unroll
        for (int ks = 0; ks < 4; ks++) {
            uint32_t afr[4][4];
#pragma unroll
            for (int mi = 0; mi < 4; mi++) {
                int off = (rowa0 + mi * 16) * 128 + (ks * 2 + cka) * 16;
                ldsm_x4(afr[mi], ab + SW128(off));
            }
            uint32_t bfr[4][4];
#pragma unroll
            for (int ng = 0; ng < 4; ng++) {
                int off = (rowb0 + ng * 16) * 128 + (ks * 2 + ckb) * 16;
                ldsm_x4(bfr[ng], bb + SW128(off));
            }
#pragma unroll
            for (int mi = 0; mi < 4; mi++)
#pragma unroll
                for (int ni = 0; ni < 8; ni++)
                    mma16816(acc[mi][ni], afr[mi],
                             bfr[ni >> 1][(ni & 1) * 2], bfr[ni >> 1][(ni & 1) * 2 + 1]);
        }
        __syncthreads();
        if (c + 3 < NC) load_chunk(c + 3);
        CP_COMMIT();
    }

    // ---------------- epilogue ----------------
    const int lrow = lid >> 2;
    const int lcol = (lid & 3) * 2;

    if (MODE == 0 || MODE == 1) {
#pragma unroll
        for (int mi = 0; mi < 4; mi++) {
#pragma unroll
            for (int ni = 0; ni < 8; ni++) {
                int col = n0 + wn * 64 + ni * 8 + lcol;
                float v0 = acc[mi][ni][0], v1 = acc[mi][ni][1];
                float v2 = acc[mi][ni][2], v3 = acc[mi][ni][3];
                if (MODE == 0) {
                    float b0 = bias[col], b1 = bias[col + 1];
                    v0 += b0; v1 += b1; v2 += b0; v3 += b1;
                } else {
                    v0 = fmaxf(v0 * RATIO, 0.0f) + FEPS;
                    v1 = fmaxf(v1 * RATIO, 0.0f) + FEPS;
                    v2 = fmaxf(v2 * RATIO, 0.0f) + FEPS;
                    v3 = fmaxf(v3 * RATIO, 0.0f) + FEPS;
                }
                int r0 = m0 + wm * 64 + mi * 16 + lrow;
                *(float2*)(C + (size_t)r0 * ldc + col)       = make_float2(v0, v1);
                *(float2*)(C + (size_t)(r0 + 8) * ldc + col) = make_float2(v2, v3);
            }
        }
    } else if (MODE == 4) {
#pragma unroll
        for (int mi = 0; mi < 4; mi++) {
#pragma unroll
            for (int rr = 0; rr < 2; rr++) {
                int r = m0 + wm * 64 + mi * 16 + rr * 8 + lrow;
                __nv_bfloat16* dst = g_qps + (size_t)r * 512;
#pragma unroll
                for (int ni = 0; ni < 8; ni++) {
                    int m = n0 + wn * 64 + ni * 8 + lcol;
                    float v0 = fmaxf(acc[mi][ni][rr * 2]     * RATIO, 0.0f) + FEPS;
                    float v1 = fmaxf(acc[mi][ni][rr * 2 + 1] * RATIO, 0.0f) + FEPS;
                    uint32_t hi, lo;
                    split_pair(v0, v1, hi, lo);
                    *(uint32_t*)(dst + m)       = hi;
                    *(uint32_t*)(dst + 256 + m) = lo;
                }
            }
        }
    } else if (MODE == 2) {
        const int region = n0 / 768;
        if (region < 2) {
            const int h = ((n0 % 768) >> 6) + wn;
#pragma unroll
            for (int mi = 0; mi < 4; mi++) {
#pragma unroll
                for (int rr = 0; rr < 2; rr++) {
                    int r = m0 + wm * 64 + mi * 16 + rr * 8 + lrow;
                    int b = r >> 12, l = r & (NL - 1);
                    __nv_bfloat16* dst = g_qks +
                        ((size_t)region * NRH + (size_t)(b * NH + h) * NL + l) * 128;
#pragma unroll
                    for (int ni = 0; ni < 8; ni++) {
                        int d = ni * 8 + lcol;
                        int col = n0 + wn * 64 + d;
                        float v0 = acc[mi][ni][rr * 2]     + bias[col];
                        float v1 = acc[mi][ni][rr * 2 + 1] + bias[col + 1];
                        uint32_t hi, lo;
                        split_pair(v0, v1, hi, lo);
                        *(uint32_t*)(dst + d)      = hi;
                        *(uint32_t*)(dst + 64 + d) = lo;
                    }
                }
            }
        } else {
#pragma unroll
            for (int mi = 0; mi < 4; mi++) {
#pragma unroll
                for (int rr = 0; rr < 2; rr++) {
                    int r = m0 + wm * 64 + mi * 16 + rr * 8 + lrow;
#pragma unroll
                    for (int ni = 0; ni < 8; ni++) {
                        int col = n0 + wn * 64 + ni * 8 + lcol;
                        float v0 = acc[mi][ni][rr * 2]     + bias[col];
                        float v1 = acc[mi][ni][rr * 2 + 1] + bias[col + 1];
                        *(float2*)(g_v + (size_t)r * NDIM + (col - 1536)) = make_float2(v0, v1);
                    }
                }
            }
        }
    } else if (MODE == 3) {
        if (wn == 1 && (lid & 3) == 0) {
#pragma unroll
            for (int mi = 0; mi < 4; mi++)
#pragma unroll
                for (int rr = 0; rr < 2; rr++)
                    den_sh[wm * 64 + mi * 16 + rr * 8 + lrow] = acc[mi][0][rr * 2];
        }
        __syncthreads();
        if (wn == 0) {
            const int bh = blockIdx.z;
            const int b = bh / NH, h = bh - b * NH;
#pragma unroll
            for (int mi = 0; mi < 4; mi++) {
#pragma unroll
                for (int rr = 0; rr < 2; rr++) {
                    int rloc = wm * 64 + mi * 16 + rr * 8 + lrow;
                    int token = b * NL + m0 + rloc;
                    float inv = 1.0f / den_sh[rloc];
                    __nv_bfloat16* dst = g_as + (size_t)token * 1536 + h * 64;
#pragma unroll
                    for (int ni = 0; ni < 8; ni++) {
                        int d = ni * 8 + lcol;
                        float v0 = acc[mi][ni][rr * 2]     * inv;
                        float v1 = acc[mi][ni][rr * 2 + 1] * inv;
                        uint32_t hi, lo;
                        split_pair(v0, v1, hi, lo);
                        *(uint32_t*)(dst + d)       = hi;
                        *(uint32_t*)(dst + 768 + d) = lo;
                    }
                }
            }
        }
    }
}

// ---------------- K3: kv_ext[b,h] = k_p^T @ [v | 1], atomic accumulate ----------------
__global__ __launch_bounds__(512) void kv_kernel() {
    const int bh = blockIdx.x;
    const int b = bh / NH, h = bh - b * NH;
    const int l0 = blockIdx.y * 256;
    const int m = threadIdx.x >> 1;
    const int half = threadIdx.x & 1;

    __shared__ float  kp_sh[8][256];
    __shared__ float4 v_sh[8][16];

    float acc[33];
#pragma unroll
    for (int i = 0; i < 33; i++) acc[i] = 0.0f;

    const float* kpb = g_kp + ((size_t)bh * NL + l0) * NM;
    const size_t vbase = (size_t)(b * NL + l0) * NDIM + h * ND;

    for (int li = 0; li < 256; li += 8) {
        {
            int idx = threadIdx.x;
            int r = idx >> 6, cg = idx & 63;
            *(float4*)&kp_sh[r][cg * 4] = *(const float4*)(kpb + (size_t)(li + r) * NM + cg * 4);
        }
        if (threadIdx.x < 128) {
            int r = threadIdx.x >> 4, dg = threadIdx.x & 15;
            v_sh[r][dg] = *(const float4*)(g_v + vbase + (size_t)(li + r) * NDIM + dg * 4);
        }
        __syncthreads();
#pragma unroll
        for (int jj = 0; jj < 8; jj++) {
            float kp = kp_sh[jj][m];
#pragma unroll
            for (int q = 0; q < 8; q++) {
                float4 v4 = v_sh[jj][half * 8 + q];
                acc[q*4+0] += kp * v4.x;
                acc[q*4+1] += kp * v4.y;
                acc[q*4+2] += kp * v4.z;
                acc[q*4+3] += kp * v4.w;
            }
            acc[32] += kp;
        }
        __syncthreads();
    }

    float* op = g_kv + ((size_t)bh * NM + m) * KV_N;
#pragma unroll
    for (int i = 0; i < 32; i++) atomicAdd(&op[half * 32 + i], acc[i]);
    if (half) atomicAdd(&op[64], acc[32]);
}

// ---------------- launch ----------------
extern "C" void kernel_launch(void* const* d_in, const int* in_sizes, int n_in,
                              void* d_out, int out_size)
{
    const float* x        = (const float*)d_in[0];
    const float* qkv_w    = (const float*)d_in[1];
    const float* qkv_b    = (const float*)d_in[2];
    const float* proj_w   = (const float*)d_in[3];
    const float* proj_b   = (const float*)d_in[4];
    const float* proj_mat = (const float*)d_in[5];
    float* out = (float*)d_out;

    float *kp_p, *kv_p;
    __nv_bfloat16 *xs_p, *ws_p, *pws_p, *pms_p, *qks_p, *qps_p, *kvt_p, *as_p;
    cudaGetSymbolAddress((void**)&kp_p,  g_kp);
    cudaGetSymbolAddress((void**)&kv_p,  g_kv);
    cudaGetSymbolAddress((void**)&xs_p,  g_xs);
    cudaGetSymbolAddress((void**)&ws_p,  g_ws);
    cudaGetSymbolAddress((void**)&pws_p, g_pws);
    cudaGetSymbolAddress((void**)&pms_p, g_pms);
    cudaGetSymbolAddress((void**)&qks_p, g_qks);
    cudaGetSymbolAddress((void**)&qps_p, g_qps);
    cudaGetSymbolAddress((void**)&kvt_p, g_kvT);
    cudaGetSymbolAddress((void**)&as_p,  g_as);

    const int SMEM_GEMM = 3 * 32768 + 1024;
    cudaFuncSetAttribute(mma_gemm<0>, cudaFuncAttributeMaxDynamicSharedMemorySize, SMEM_GEMM);
    cudaFuncSetAttribute(mma_gemm<1>, cudaFuncAttributeMaxDynamicSharedMemorySize, SMEM_GEMM);
    cudaFuncSetAttribute(mma_gemm<2>, cudaFuncAttributeMaxDynamicSharedMemorySize, SMEM_GEMM);
    cudaFuncSetAttribute(mma_gemm<3>, cudaFuncAttributeMaxDynamicSharedMemorySize, SMEM_GEMM);
    cudaFuncSetAttribute(mma_gemm<4>, cudaFuncAttributeMaxDynamicSharedMemorySize, SMEM_GEMM);

    const int kvn = NB * NH * NM * KV_N;
    zero_kernel<<<(kvn + 255) / 256, 256>>>(kv_p, kvn);

    split4_kernel<<<8192, 256>>>(x,        xs_p,  768, NTOK * 768 / 4);
    split4_kernel<<<2048, 256>>>(qkv_w,    ws_p,  768, 2304 * 768 / 4);
    split4_kernel<<<1024, 256>>>(proj_w,   pws_p, 768, 768 * 768 / 4);
    split4_kernel<<<  64, 256>>>(proj_mat, pms_p, 64,  256 * 64 / 4);

    // K1: qkv = x @ qkv_w^T + b; scatter q,k split bf16 + v fp32
    mma_gemm<2><<<dim3(18, NTOK / 128), 128, SMEM_GEMM>>>(
        xs_p, 1536, 0, ws_p, 1536, 0, nullptr, 0, qkv_b, 768);

    // K2-q: q_p -> split bf16 g_qps
    mma_gemm<4><<<dim3(2, NRH / 128), 128, SMEM_GEMM>>>(
        qks_p, 128, 0, pms_p, 128, 0, nullptr, 0, nullptr, 64);
    // K2-k: k_p -> fp32 g_kp
    mma_gemm<1><<<dim3(2, NRH / 128), 128, SMEM_GEMM>>>(
        qks_p + (size_t)NRH * 128, 128, 0, pms_p, 128, 0, kp_p, NM, nullptr, 64);

    // K3: kv_ext = k_p^T @ [v | 1]
    kv_kernel<<<dim3(NB * NH, NL / 256), 512>>>();

    // kv -> kvT split bf16
    kvt_kernel<<<NB * NH, 256>>>();

    // K4: att = (q_p @ kv) / den -> split bf16 g_as   (HMMA, z = bh)
    mma_gemm<3><<<dim3(1, NL / 128, NB * NH), 128, SMEM_GEMM>>>(
        qps_p, 512, (size_t)NL * 512, kvt_p, 512, (size_t)128 * 512,
        nullptr, 0, nullptr, 256);

    // K5: out = att @ proj_w^T + proj_b
    mma_gemm<0><<<dim3(NDIM / 128, NTOK / 128), 128, SMEM_GEMM>>>(
        as_p, 1536, 0, pws_p, 1536, 0, out, NDIM, proj_b, 768);
}

// round 8
// speedup vs baseline: 2.3490x; 1.3013x over previous
#include <cuda_runtime.h>
#include <cuda_bf16.h>
#include <cstdint>

// ---------------- problem constants ----------------
#define NB   8
#define NL   4096
#define NDIM 768
#define NH   12
#define ND   64
#define NM   256
#define NTOK (NB * NL)     // 32768
#define NRH  (NTOK * NH)   // 393216
#define KV_N 65
#define FEPS 1.0e-3f
#define RATIO 0.0625f

// ---------------- scratch (static device globals; no allocs) ----------------
__device__ __align__(128) float g_xr [(size_t)NTOK * NDIM];          // 100 MB  x, tf32-rounded
__device__ __align__(128) float g_wr [(size_t)2304 * NDIM];          // 7 MB    qkv_w rounded
__device__ __align__(128) float g_pwr[(size_t)NDIM * NDIM];          // 2.4 MB  proj_w rounded
__device__ __align__(128) float g_pmr[(size_t)NM * ND];              // 64 KB   proj_mat rounded
__device__ __align__(128) float g_qk [(size_t)2 * NRH * ND];         // 200 MB  q|k rounded [sel][bh,l][64]
__device__ __align__(128) float g_v  [(size_t)NTOK * NDIM];          // 100 MB  v fp32 [token][768]
__device__ __align__(128) float g_qp [(size_t)NRH * NM];             // 402 MB  q_p rounded [bh,l][256]
__device__ __align__(128) float g_kp [(size_t)NRH * NM];             // 402 MB  k_p fp32 [bh,l][256]
__device__ __align__(128) float g_kv [(size_t)NB * NH * NM * KV_N];  // 6.4 MB  kv fp32 [bh][m][65]
__device__ __align__(128) float g_kvT[(size_t)NB * NH * 128 * NM];   // 12.6 MB kv^T rounded [bh][128][256]
__device__ __align__(128) float g_att[(size_t)NTOK * NDIM];          // 100 MB  att rounded [token][768]

// ---------------- PTX helpers ----------------
__device__ __forceinline__ uint32_t s2u(const void* p) {
    uint32_t a;
    asm("{ .reg .u64 t; cvta.to.shared.u64 t, %1; cvt.u32.u64 %0, t; }" : "=r"(a) : "l"(p));
    return a;
}
__device__ __forceinline__ void cpa16(uint32_t s, const void* g) {
    asm volatile("cp.async.cg.shared.global [%0], [%1], 16;\n" :: "r"(s), "l"(g));
}
#define CP_COMMIT() asm volatile("cp.async.commit_group;\n" ::: "memory")
#define CP_WAIT(n)  asm volatile("cp.async.wait_group %0;\n" :: "n"(n) : "memory")
#define SW128(o) ((o) ^ (((o) >> 3) & 0x70))

__device__ __forceinline__ void ldsm_x4(uint32_t* r, uint32_t addr) {
    asm volatile("ldmatrix.sync.aligned.m8n8.x4.shared.b16 {%0,%1,%2,%3}, [%4];"
                 : "=r"(r[0]), "=r"(r[1]), "=r"(r[2]), "=r"(r[3]) : "r"(addr));
}
// m16n8k8 tf32 mma: A 4 regs, B 2 regs, fp32 accum
__device__ __forceinline__ void mma_tf32(float* d, const uint32_t* a, uint32_t b0, uint32_t b1) {
    asm volatile(
        "mma.sync.aligned.m16n8k8.row.col.f32.tf32.tf32.f32 "
        "{%0,%1,%2,%3}, {%4,%5,%6,%7}, {%8,%9}, {%0,%1,%2,%3};"
        : "+f"(d[0]), "+f"(d[1]), "+f"(d[2]), "+f"(d[3])
        : "r"(a[0]), "r"(a[1]), "r"(a[2]), "r"(a[3]), "r"(b0), "r"(b1));
}
// round-to-nearest tf32 (mantissa 10 bits), returned as fp32 bit pattern
__device__ __forceinline__ float rna(float v) {
    uint32_t u;
    asm("cvt.rna.tf32.f32 %0, %1;" : "=r"(u) : "f"(v));
    return __uint_as_float(u);
}

// ---------------- K0: zero ----------------
__global__ void zero_kernel(float* __restrict__ p, int n) {
    int i = blockIdx.x * blockDim.x + threadIdx.x;
    if (i < n) p[i] = 0.0f;
}

// ---------------- fp32 -> tf32-rounded fp32 (vectorized grid-stride) ----------------
__global__ void rna4_kernel(const float* __restrict__ src, float* __restrict__ dst, int total4) {
    for (int i = blockIdx.x * blockDim.x + threadIdx.x; i < total4; i += gridDim.x * blockDim.x) {
        float4 v = *(const float4*)(src + (size_t)i * 4);
        v.x = rna(v.x); v.y = rna(v.y); v.z = rna(v.z); v.w = rna(v.w);
        *(float4*)(dst + (size_t)i * 4) = v;
    }
}

// ---------------- kv -> kvT rounded, padded to 128 n-rows ----------------
__global__ void kvt_kernel() {
    const int bh = blockIdx.x;
    const float* src = g_kv + (size_t)bh * NM * KV_N;
    float* dst = g_kvT + (size_t)bh * 128 * NM;
    for (int i = threadIdx.x; i < 128 * NM; i += 256) {
        int n = i >> 8;          // 0..127 (kv col | den | pad)
        int m = i & 255;         // feature
        float v = (n < KV_N) ? src[(size_t)m * KV_N + n] : 0.0f;
        dst[(size_t)n * NM + m] = rna(v);
    }
}

// ---------------- 1xTF32 GEMM via mma.sync ----------------
// C[M,N] = A[M,K] · B[N,K]^T, operands fp32 bit patterns (pre-rounded to tf32).
// Tile BM=BN=128, BK=32 fp32 (128B rows). 128 threads = 4 warps (2m x 2n),
// warp tile 64x64. 3-stage cp.async pipeline, SW128 smem, ldmatrix fragments.
// MODE 0: C = acc + bias (fp32, final)               [K5]
// MODE 1: C = relu(acc*RATIO)+FEPS (fp32)            [K2-k]
// MODE 2: qkv scatter: q,k rounded -> g_qk; v -> g_v [K1]
// MODE 3: attn: den=col64, divide, rounded -> g_att  [K4]
// MODE 4: relu(acc*RATIO)+FEPS rounded -> g_qp       [K2-q]
template <int MODE>
__global__ __launch_bounds__(128, 2) void mma_gemm(
    const float* __restrict__ A, int lda, size_t aZ,
    const float* __restrict__ B, int ldb, size_t bZ,
    float* __restrict__ C, int ldc,
    const float* __restrict__ bias,
    int kdim)
{
    extern __shared__ char dynsm[];
    __shared__ float den_sh[128];
    const uint32_t sbase = (s2u(dynsm) + 1023u) & ~1023u;
    const int tid = threadIdx.x;
    const int wid = tid >> 5, lid = tid & 31;
    const int wm = wid & 1, wn = wid >> 1;
    const int n0 = blockIdx.x * 128;
    const int m0 = blockIdx.y * 128;
    A += (size_t)blockIdx.z * aZ;
    B += (size_t)blockIdx.z * bZ;
    const int NC = kdim >> 5;            // 32 fp32 per chunk

    float acc[4][8][4];
#pragma unroll
    for (int i = 0; i < 4; i++)
#pragma unroll
        for (int j = 0; j < 8; j++)
#pragma unroll
            for (int q = 0; q < 4; q++) acc[i][j][q] = 0.0f;

    auto load_chunk = [&](int c) {
        int slot = c % 3;
        uint32_t ab = sbase + (uint32_t)slot * 32768u;
        uint32_t bb = ab + 16384u;
        const float* ap = A + (size_t)m0 * lda + c * 32;
        const float* bp = B + (size_t)n0 * ldb + c * 32;
#pragma unroll
        for (int i = 0; i < 8; i++) {
            int idx = tid + (i << 7);
            int row = idx >> 3, ch = idx & 7;
            cpa16(ab + SW128(row * 128 + ch * 16), ap + (size_t)row * lda + ch * 4);
        }
#pragma unroll
        for (int i = 0; i < 8; i++) {
            int idx = tid + (i << 7);
            int row = idx >> 3, ch = idx & 7;
            cpa16(bb + SW128(row * 128 + ch * 16), bp + (size_t)row * ldb + ch * 4);
        }
    };

#pragma unroll
    for (int i = 0; i < 3; i++) {
        if (i < NC) load_chunk(i);
        CP_COMMIT();
    }

    // ldmatrix lane geometry
    const int lt = lid >> 3;             // tile 0..3 within x4
    const int lr = lid & 7;              // row within 8x8 tile
    // A tiles: t0 rows 0-7 k0-3 | t1 rows 8-15 k0-3 | t2 rows 0-7 k4-7 | t3 rows 8-15 k4-7
    const int rowa0 = wm * 64 + ((lt & 1) << 3) + lr;    // + mi*16
    const int byta  = (lt >> 1) * 16;
    // B tiles: t0 n0-7 k0-3 | t1 n0-7 k4-7 | t2 n8-15 k0-3 | t3 n8-15 k4-7
    const int rowb0 = wn * 64 + ((lt >> 1) << 3) + lr;   // + ng*16
    const int bytb  = (lt & 1) * 16;

    for (int c = 0; c < NC; c++) {
        CP_WAIT(2);
        __syncthreads();

        uint32_t ab = sbase + (uint32_t)(c % 3) * 32768u;
        uint32_t bb = ab + 16384u;
#pragma unroll
        for (int ks = 0; ks < 4; ks++) {     // 4 x k8 per 32-chunk
            uint32_t afr[4][4];
#pragma unroll
            for (int mi = 0; mi < 4; mi++) {
                int off = (rowa0 + mi * 16) * 128 + ks * 32 + byta;
                ldsm_x4(afr[mi], ab + SW128(off));
            }
            uint32_t bfr[4][4];                // [ng]: {b0,b1 of n8 blk0, b0,b1 of blk1}
#pragma unroll
            for (int ng = 0; ng < 4; ng++) {
                int off = (rowb0 + ng * 16) * 128 + ks * 32 + bytb;
                ldsm_x4(bfr[ng], bb + SW128(off));
            }
#pragma unroll
            for (int mi = 0; mi < 4; mi++)
#pragma unroll
                for (int ni = 0; ni < 8; ni++)
                    mma_tf32(acc[mi][ni], afr[mi],
                             bfr[ni >> 1][(ni & 1) * 2], bfr[ni >> 1][(ni & 1) * 2 + 1]);
        }
        __syncthreads();
        if (c + 3 < NC) load_chunk(c + 3);
        CP_COMMIT();
    }

    // ---------------- epilogue ----------------
    const int lrow = lid >> 2;
    const int lcol = (lid & 3) * 2;

    if (MODE == 0 || MODE == 1) {
#pragma unroll
        for (int mi = 0; mi < 4; mi++) {
#pragma unroll
            for (int ni = 0; ni < 8; ni++) {
                int col = n0 + wn * 64 + ni * 8 + lcol;
                float v0 = acc[mi][ni][0], v1 = acc[mi][ni][1];
                float v2 = acc[mi][ni][2], v3 = acc[mi][ni][3];
                if (MODE == 0) {
                    float b0 = bias[col], b1 = bias[col + 1];
                    v0 += b0; v1 += b1; v2 += b0; v3 += b1;
                } else {
                    v0 = fmaxf(v0 * RATIO, 0.0f) + FEPS;
                    v1 = fmaxf(v1 * RATIO, 0.0f) + FEPS;
                    v2 = fmaxf(v2 * RATIO, 0.0f) + FEPS;
                    v3 = fmaxf(v3 * RATIO, 0.0f) + FEPS;
                }
                int r0 = m0 + wm * 64 + mi * 16 + lrow;
                *(float2*)(C + (size_t)r0 * ldc + col)       = make_float2(v0, v1);
                *(float2*)(C + (size_t)(r0 + 8) * ldc + col) = make_float2(v2, v3);
            }
        }
    } else if (MODE == 4) {
#pragma unroll
        for (int mi = 0; mi < 4; mi++) {
#pragma unroll
            for (int rr = 0; rr < 2; rr++) {
                int r = m0 + wm * 64 + mi * 16 + rr * 8 + lrow;
                float* dst = g_qp + (size_t)r * NM;
#pragma unroll
                for (int ni = 0; ni < 8; ni++) {
                    int m = n0 + wn * 64 + ni * 8 + lcol;
                    float v0 = rna(fmaxf(acc[mi][ni][rr * 2]     * RATIO, 0.0f) + FEPS);
                    float v1 = rna(fmaxf(acc[mi][ni][rr * 2 + 1] * RATIO, 0.0f) + FEPS);
                    *(float2*)(dst + m) = make_float2(v0, v1);
                }
            }
        }
    } else if (MODE == 2) {
        const int region = n0 / 768;               // 0=q, 1=k, 2=v
        if (region < 2) {
            const int h = ((n0 % 768) >> 6) + wn;
#pragma unroll
            for (int mi = 0; mi < 4; mi++) {
#pragma unroll
                for (int rr = 0; rr < 2; rr++) {
                    int r = m0 + wm * 64 + mi * 16 + rr * 8 + lrow;
                    int b = r >> 12, l = r & (NL - 1);
                    float* dst = g_qk +
                        ((size_t)region * NRH + (size_t)(b * NH + h) * NL + l) * ND;
#pragma unroll
                    for (int ni = 0; ni < 8; ni++) {
                        int d = ni * 8 + lcol;
                        int col = n0 + wn * 64 + d;
                        float v0 = rna(acc[mi][ni][rr * 2]     + bias[col]);
                        float v1 = rna(acc[mi][ni][rr * 2 + 1] + bias[col + 1]);
                        *(float2*)(dst + d) = make_float2(v0, v1);
                    }
                }
            }
        } else {
#pragma unroll
            for (int mi = 0; mi < 4; mi++) {
#pragma unroll
                for (int rr = 0; rr < 2; rr++) {
                    int r = m0 + wm * 64 + mi * 16 + rr * 8 + lrow;
#pragma unroll
                    for (int ni = 0; ni < 8; ni++) {
                        int col = n0 + wn * 64 + ni * 8 + lcol;
                        float v0 = acc[mi][ni][rr * 2]     + bias[col];
                        float v1 = acc[mi][ni][rr * 2 + 1] + bias[col + 1];
                        *(float2*)(g_v + (size_t)r * NDIM + (col - 1536)) = make_float2(v0, v1);
                    }
                }
            }
        }
    } else if (MODE == 3) {
        if (wn == 1 && (lid & 3) == 0) {
#pragma unroll
            for (int mi = 0; mi < 4; mi++)
#pragma unroll
                for (int rr = 0; rr < 2; rr++)
                    den_sh[wm * 64 + mi * 16 + rr * 8 + lrow] = acc[mi][0][rr * 2];
        }
        __syncthreads();
        if (wn == 0) {
            const int bh = blockIdx.z;
            const int b = bh / NH, h = bh - b * NH;
#pragma unroll
            for (int mi = 0; mi < 4; mi++) {
#pragma unroll
                for (int rr = 0; rr < 2; rr++) {
                    int rloc = wm * 64 + mi * 16 + rr * 8 + lrow;
                    int token = b * NL + m0 + rloc;
                    float inv = 1.0f / den_sh[rloc];
                    float* dst = g_att + (size_t)token * NDIM + h * ND;
#pragma unroll
                    for (int ni = 0; ni < 8; ni++) {
                        int d = ni * 8 + lcol;
                        float v0 = rna(acc[mi][ni][rr * 2]     * inv);
                        float v1 = rna(acc[mi][ni][rr * 2 + 1] * inv);
                        *(float2*)(dst + d) = make_float2(v0, v1);
                    }
                }
            }
        }
    }
}

// ---------------- K3: kv_ext[b,h] = k_p^T @ [v | 1], atomic accumulate ----------------
__global__ __launch_bounds__(512) void kv_kernel() {
    const int bh = blockIdx.x;
    const int b = bh / NH, h = bh - b * NH;
    const int l0 = blockIdx.y * 256;
    const int m = threadIdx.x >> 1;
    const int half = threadIdx.x & 1;

    __shared__ float  kp_sh[8][256];
    __shared__ float4 v_sh[8][16];

    float acc[33];
#pragma unroll
    for (int i = 0; i < 33; i++) acc[i] = 0.0f;

    const float* kpb = g_kp + ((size_t)bh * NL + l0) * NM;
    const size_t vbase = (size_t)(b * NL + l0) * NDIM + h * ND;

    for (int li = 0; li < 256; li += 8) {
        {
            int idx = threadIdx.x;
            int r = idx >> 6, cg = idx & 63;
            *(float4*)&kp_sh[r][cg * 4] = *(const float4*)(kpb + (size_t)(li + r) * NM + cg * 4);
        }
        if (threadIdx.x < 128) {
            int r = threadIdx.x >> 4, dg = threadIdx.x & 15;
            v_sh[r][dg] = *(const float4*)(g_v + vbase + (size_t)(li + r) * NDIM + dg * 4);
        }
        __syncthreads();
#pragma unroll
        for (int jj = 0; jj < 8; jj++) {
            float kp = kp_sh[jj][m];
#pragma unroll
            for (int q = 0; q < 8; q++) {
                float4 v4 = v_sh[jj][half * 8 + q];
                acc[q*4+0] += kp * v4.x;
                acc[q*4+1] += kp * v4.y;
                acc[q*4+2] += kp * v4.z;
                acc[q*4+3] += kp * v4.w;
            }
            acc[32] += kp;
        }
        __syncthreads();
    }

    float* op = g_kv + ((size_t)bh * NM + m) * KV_N;
#pragma unroll
    for (int i = 0; i < 32; i++) atomicAdd(&op[half * 32 + i], acc[i]);
    if (half) atomicAdd(&op[64], acc[32]);
}

// ---------------- launch ----------------
extern "C" void kernel_launch(void* const* d_in, const int* in_sizes, int n_in,
                              void* d_out, int out_size)
{
    const float* x        = (const float*)d_in[0];
    const float* qkv_w    = (const float*)d_in[1];
    const float* qkv_b    = (const float*)d_in[2];
    const float* proj_w   = (const float*)d_in[3];
    const float* proj_b   = (const float*)d_in[4];
    const float* proj_mat = (const float*)d_in[5];
    float* out = (float*)d_out;

    float *xr_p, *wr_p, *pwr_p, *pmr_p, *qk_p, *qp_p, *kp_p, *kv_p, *kvt_p, *att_p;
    cudaGetSymbolAddress((void**)&xr_p,  g_xr);
    cudaGetSymbolAddress((void**)&wr_p,  g_wr);
    cudaGetSymbolAddress((void**)&pwr_p, g_pwr);
    cudaGetSymbolAddress((void**)&pmr_p, g_pmr);
    cudaGetSymbolAddress((void**)&qk_p,  g_qk);
    cudaGetSymbolAddress((void**)&qp_p,  g_qp);
    cudaGetSymbolAddress((void**)&kp_p,  g_kp);
    cudaGetSymbolAddress((void**)&kv_p,  g_kv);
    cudaGetSymbolAddress((void**)&kvt_p, g_kvT);
    cudaGetSymbolAddress((void**)&att_p, g_att);

    const int SMEM_GEMM = 3 * 32768 + 1024;
    cudaFuncSetAttribute(mma_gemm<0>, cudaFuncAttributeMaxDynamicSharedMemorySize, SMEM_GEMM);
    cudaFuncSetAttribute(mma_gemm<1>, cudaFuncAttributeMaxDynamicSharedMemorySize, SMEM_GEMM);
    cudaFuncSetAttribute(mma_gemm<2>, cudaFuncAttributeMaxDynamicSharedMemorySize, SMEM_GEMM);
    cudaFuncSetAttribute(mma_gemm<3>, cudaFuncAttributeMaxDynamicSharedMemorySize, SMEM_GEMM);
    cudaFuncSetAttribute(mma_gemm<4>, cudaFuncAttributeMaxDynamicSharedMemorySize, SMEM_GEMM);

    const int kvn = NB * NH * NM * KV_N;
    zero_kernel<<<(kvn + 255) / 256, 256>>>(kv_p, kvn);

    // tf32-round the raw inputs (RNA halves the truncation error)
    rna4_kernel<<<4096, 256>>>(x,        xr_p,  NTOK * NDIM / 4);
    rna4_kernel<<<1024, 256>>>(qkv_w,    wr_p,  2304 * NDIM / 4);
    rna4_kernel<<< 512, 256>>>(proj_w,   pwr_p, NDIM * NDIM / 4);
    rna4_kernel<<<  16, 256>>>(proj_mat, pmr_p, NM * ND / 4);

    // K1: qkv = x @ qkv_w^T + b; scatter q,k (rounded) + v (fp32)
    mma_gemm<2><<<dim3(18, NTOK / 128), 128, SMEM_GEMM>>>(
        xr_p, NDIM, 0, wr_p, NDIM, 0, nullptr, 0, qkv_b, NDIM);

    // K2-q: q_p -> g_qp (rounded)
    mma_gemm<4><<<dim3(2, NRH / 128), 128, SMEM_GEMM>>>(
        qk_p, ND, 0, pmr_p, ND, 0, nullptr, 0, nullptr, ND);
    // K2-k: k_p -> g_kp (fp32)
    mma_gemm<1><<<dim3(2, NRH / 128), 128, SMEM_GEMM>>>(
        qk_p + (size_t)NRH * ND, ND, 0, pmr_p, ND, 0, kp_p, NM, nullptr, ND);

    // K3: kv_ext = k_p^T @ [v | 1]
    kv_kernel<<<dim3(NB * NH, NL / 256), 512>>>();

    // kv -> kvT (rounded, padded to 128 rows)
    kvt_kernel<<<NB * NH, 256>>>();

    // K4: att = (q_p @ kv) / den -> g_att (rounded); z = bh
    mma_gemm<3><<<dim3(1, NL / 128, NB * NH), 128, SMEM_GEMM>>>(
        qp_p, NM, (size_t)NL * NM, kvt_p, NM, (size_t)128 * NM,
        nullptr, 0, nullptr, NM);

    // K5: out = att @ proj_w^T + proj_b
    mma_gemm<0><<<dim3(NDIM / 128, NTOK / 128), 128, SMEM_GEMM>>>(
        att_p, NDIM, 0, pwr_p, NDIM, 0, out, NDIM, proj_b, NDIM);
}

// round 9
// speedup vs baseline: 3.6420x; 1.5504x over previous
#include <cuda_runtime.h>
#include <cstdint>

// ---------------- problem constants ----------------
#define NB   8
#define NL   4096
#define NDIM 768
#define NH   12
#define ND   64
#define NM   256
#define NTOK (NB * NL)     // 32768
#define NRH  (NTOK * NH)   // 393216
#define FEPS 1.0e-3f
#define RATIO 0.0625f

// ---------------- scratch (static device globals; no allocs) ----------------
__device__ __align__(128) float g_xr [(size_t)NTOK * NDIM];          // 100 MB  x tf32-rounded
__device__ __align__(128) float g_wr [(size_t)2304 * NDIM];          // 7 MB
__device__ __align__(128) float g_pwr[(size_t)NDIM * NDIM];          // 2.4 MB
__device__ __align__(128) float g_pmr[(size_t)NM * ND];              // 64 KB
__device__ __align__(128) float g_qk [(size_t)2 * NRH * ND];         // 200 MB  q|k rounded [sel][bh,l][64]
__device__ __align__(128) float g_qp [(size_t)NRH * NM];             // 402 MB  q_p rounded [bh,l][256]
__device__ __align__(128) float g_kpT[(size_t)NB * NH * NM * NL];    // 402 MB  k_p^T rounded [bh][m][l]
__device__ __align__(128) float g_vT [(size_t)NB * NH * 128 * NL];   // 200 MB  v^T rounded [bh][d|1|0][l]
__device__ __align__(128) float g_kv [(size_t)NB * NH * NM * 128];   // 12.6 MB kv fp32 [bh][m][n]
__device__ __align__(128) float g_kvT[(size_t)NB * NH * 128 * NM];   // 12.6 MB kv^T rounded [bh][n][m]
__device__ __align__(128) float g_att[(size_t)NTOK * NDIM];          // 100 MB  att rounded

// ---------------- PTX helpers ----------------
__device__ __forceinline__ uint32_t s2u(const void* p) {
    uint32_t a;
    asm("{ .reg .u64 t; cvta.to.shared.u64 t, %1; cvt.u32.u64 %0, t; }" : "=r"(a) : "l"(p));
    return a;
}
__device__ __forceinline__ void cpa16(uint32_t s, const void* g) {
    asm volatile("cp.async.cg.shared.global [%0], [%1], 16;\n" :: "r"(s), "l"(g));
}
#define CP_COMMIT() asm volatile("cp.async.commit_group;\n" ::: "memory")
#define CP_WAIT(n)  asm volatile("cp.async.wait_group %0;\n" :: "n"(n) : "memory")
#define SW128(o) ((o) ^ (((o) >> 3) & 0x70))

__device__ __forceinline__ void ldsm_x4(uint32_t* r, uint32_t addr) {
    asm volatile("ldmatrix.sync.aligned.m8n8.x4.shared.b16 {%0,%1,%2,%3}, [%4];"
                 : "=r"(r[0]), "=r"(r[1]), "=r"(r[2]), "=r"(r[3]) : "r"(addr));
}
__device__ __forceinline__ void mma_tf32(float* d, const uint32_t* a, uint32_t b0, uint32_t b1) {
    asm volatile(
        "mma.sync.aligned.m16n8k8.row.col.f32.tf32.tf32.f32 "
        "{%0,%1,%2,%3}, {%4,%5,%6,%7}, {%8,%9}, {%0,%1,%2,%3};"
        : "+f"(d[0]), "+f"(d[1]), "+f"(d[2]), "+f"(d[3])
        : "r"(a[0]), "r"(a[1]), "r"(a[2]), "r"(a[3]), "r"(b0), "r"(b1));
}
__device__ __forceinline__ float rna(float v) {
    uint32_t u;
    asm("cvt.rna.tf32.f32 %0, %1;" : "=r"(u) : "f"(v));
    return __uint_as_float(u);
}

// ---------------- zero / init ----------------
__global__ void zero_kernel(float* __restrict__ p, int n) {
    int i = blockIdx.x * blockDim.x + threadIdx.x;
    if (i < n) p[i] = 0.0f;
}
// g_vT rows 64..127: row 64 = ones (k_sum column), rows 65..127 = zero
__global__ void initvt_kernel() {
    const int total = NB * NH * 64 * (NL / 4);
    for (int i = blockIdx.x * blockDim.x + threadIdx.x; i < total; i += gridDim.x * blockDim.x) {
        int lp = i & (NL / 4 - 1);
        int rp = i >> 10;            // bh*64 + (row-64)
        int row = rp & 63;
        int bh = rp >> 6;
        float v = (row == 0) ? 1.0f : 0.0f;
        *(float4*)(g_vT + ((size_t)bh * 128 + 64 + row) * NL + lp * 4) = make_float4(v, v, v, v);
    }
}

// ---------------- fp32 -> tf32-rounded (RNA) ----------------
__global__ void rna4_kernel(const float* __restrict__ src, float* __restrict__ dst, int total4) {
    for (int i = blockIdx.x * blockDim.x + threadIdx.x; i < total4; i += gridDim.x * blockDim.x) {
        float4 v = *(const float4*)(src + (size_t)i * 4);
        v.x = rna(v.x); v.y = rna(v.y); v.z = rna(v.z); v.w = rna(v.w);
        *(float4*)(dst + (size_t)i * 4) = v;
    }
}

// ---------------- kv [bh][m][n] -> kvT [bh][n][m] rounded ----------------
__global__ void kvt_kernel() {
    const int bh = blockIdx.x;
    const float* src = g_kv + (size_t)bh * NM * 128;
    float* dst = g_kvT + (size_t)bh * 128 * NM;
    for (int i = threadIdx.x; i < 128 * NM; i += 256) {
        int n = i >> 8;
        int m = i & 255;
        dst[i] = rna(src[(size_t)m * 128 + n]);
    }
}

// ---------------- 1xTF32 GEMM via mma.sync ----------------
// Tile BM=BN=128, BK=32 fp32 (128B rows). 128 thr = 4 warps (2m x 2n), warp 64x64.
// 3-stage cp.async + per-warp fragment double-buffering. SW128 smem, ldmatrix.
// MODE 0: C = acc + bias (final)                       [K5]
// MODE 2: qkv scatter: q,k rounded -> g_qk; v^T -> g_vT [K1]
// MODE 3: attn: den=col64, divide, rounded -> g_att    [K4]
// MODE 4: relu rounded -> g_qp                          [K2-q]
// MODE 5: relu rounded, transposed -> g_kpT             [K2-k]
// MODE 6: split-K atomic accumulate -> g_kv             [K3]
template <int MODE>
__global__ __launch_bounds__(128, 2) void mma_gemm(
    const float* __restrict__ A, int lda, size_t aZ,
    const float* __restrict__ B, int ldb, size_t bZ,
    float* __restrict__ C, int ldc,
    const float* __restrict__ bias,
    int kdim)
{
    extern __shared__ char dynsm[];
    __shared__ float den_sh[128];
    const uint32_t sbase = (s2u(dynsm) + 1023u) & ~1023u;
    const int tid = threadIdx.x;
    const int wid = tid >> 5, lid = tid & 31;
    const int wm = wid & 1, wn = wid >> 1;
    const int n0 = blockIdx.x * 128;
    const int m0 = blockIdx.y * 128;
    if (MODE == 6) {
        int bh = blockIdx.z >> 3, seg = blockIdx.z & 7;
        A = g_kpT + (size_t)bh * NM * NL + seg * 512;
        B = g_vT  + (size_t)bh * 128 * NL + seg * 512;
    } else {
        A += (size_t)blockIdx.z * aZ;
        B += (size_t)blockIdx.z * bZ;
    }
    const int NC = kdim >> 5;

    float acc[4][8][4];
#pragma unroll
    for (int i = 0; i < 4; i++)
#pragma unroll
        for (int j = 0; j < 8; j++)
#pragma unroll
            for (int q = 0; q < 4; q++) acc[i][j][q] = 0.0f;

    auto load_chunk = [&](int c) {
        int slot = c % 3;
        uint32_t ab = sbase + (uint32_t)slot * 32768u;
        uint32_t bb = ab + 16384u;
        const float* ap = A + (size_t)m0 * lda + c * 32;
        const float* bp = B + (size_t)n0 * ldb + c * 32;
#pragma unroll
        for (int i = 0; i < 8; i++) {
            int idx = tid + (i << 7);
            int row = idx >> 3, ch = idx & 7;
            cpa16(ab + SW128(row * 128 + ch * 16), ap + (size_t)row * lda + ch * 4);
        }
#pragma unroll
        for (int i = 0; i < 8; i++) {
            int idx = tid + (i << 7);
            int row = idx >> 3, ch = idx & 7;
            cpa16(bb + SW128(row * 128 + ch * 16), bp + (size_t)row * ldb + ch * 4);
        }
    };

#pragma unroll
    for (int i = 0; i < 3; i++) {
        if (i < NC) load_chunk(i);
        CP_COMMIT();
    }

    const int lt = lid >> 3;
    const int lr = lid & 7;
    const int rowa0 = wm * 64 + ((lt & 1) << 3) + lr;
    const int byta  = (lt >> 1) * 16;
    const int rowb0 = wn * 64 + ((lt >> 1) << 3) + lr;
    const int bytb  = (lt & 1) * 16;

    uint32_t afr[2][4][4], bfr[2][4][4];
    auto ld_frags = [&](uint32_t ab, uint32_t bb, int ks, int buf) {
#pragma unroll
        for (int mi = 0; mi < 4; mi++) {
            int off = (rowa0 + mi * 16) * 128 + ks * 32 + byta;
            ldsm_x4(afr[buf][mi], ab + SW128(off));
        }
#pragma unroll
        for (int ng = 0; ng < 4; ng++) {
            int off = (rowb0 + ng * 16) * 128 + ks * 32 + bytb;
            ldsm_x4(bfr[buf][ng], bb + SW128(off));
        }
    };

    for (int c = 0; c < NC; c++) {
        CP_WAIT(2);
        __syncthreads();

        uint32_t ab = sbase + (uint32_t)(c % 3) * 32768u;
        uint32_t bb = ab + 16384u;
        ld_frags(ab, bb, 0, 0);
#pragma unroll
        for (int ks = 0; ks < 4; ks++) {
            int cur = ks & 1;
            if (ks < 3) ld_frags(ab, bb, ks + 1, cur ^ 1);
#pragma unroll
            for (int mi = 0; mi < 4; mi++)
#pragma unroll
                for (int ni = 0; ni < 8; ni++)
                    mma_tf32(acc[mi][ni], afr[cur][mi],
                             bfr[cur][ni >> 1][(ni & 1) * 2], bfr[cur][ni >> 1][(ni & 1) * 2 + 1]);
        }
        __syncthreads();
        if (c + 3 < NC) load_chunk(c + 3);
        CP_COMMIT();
    }

    // ---------------- epilogue ----------------
    const int lrow = lid >> 2;
    const int lcol = (lid & 3) * 2;

    if (MODE == 0) {
#pragma unroll
        for (int mi = 0; mi < 4; mi++) {
#pragma unroll
            for (int ni = 0; ni < 8; ni++) {
                int col = n0 + wn * 64 + ni * 8 + lcol;
                float b0 = bias[col], b1 = bias[col + 1];
                int r0 = m0 + wm * 64 + mi * 16 + lrow;
                *(float2*)(C + (size_t)r0 * ldc + col) =
                    make_float2(acc[mi][ni][0] + b0, acc[mi][ni][1] + b1);
                *(float2*)(C + (size_t)(r0 + 8) * ldc + col) =
                    make_float2(acc[mi][ni][2] + b0, acc[mi][ni][3] + b1);
            }
        }
    } else if (MODE == 4) {
#pragma unroll
        for (int mi = 0; mi < 4; mi++) {
#pragma unroll
            for (int rr = 0; rr < 2; rr++) {
                int r = m0 + wm * 64 + mi * 16 + rr * 8 + lrow;
                float* dst = g_qp + (size_t)r * NM;
#pragma unroll
                for (int ni = 0; ni < 8; ni++) {
                    int m = n0 + wn * 64 + ni * 8 + lcol;
                    float v0 = rna(fmaxf(acc[mi][ni][rr * 2]     * RATIO, 0.0f) + FEPS);
                    float v1 = rna(fmaxf(acc[mi][ni][rr * 2 + 1] * RATIO, 0.0f) + FEPS);
                    *(float2*)(dst + m) = make_float2(v0, v1);
                }
            }
        }
    } else if (MODE == 5) {
        // k_p transposed -> g_kpT[bh][m][l], staged through smem
        float* st = (float*)dynsm;   // [128 l][129]
#pragma unroll
        for (int mi = 0; mi < 4; mi++) {
#pragma unroll
            for (int rr = 0; rr < 2; rr++) {
                int row = wm * 64 + mi * 16 + rr * 8 + lrow;
#pragma unroll
                for (int ni = 0; ni < 8; ni++) {
                    int cl = wn * 64 + ni * 8 + lcol;
                    st[row * 129 + cl]     = rna(fmaxf(acc[mi][ni][rr * 2]     * RATIO, 0.0f) + FEPS);
                    st[row * 129 + cl + 1] = rna(fmaxf(acc[mi][ni][rr * 2 + 1] * RATIO, 0.0f) + FEPS);
                }
            }
        }
        __syncthreads();
        int bh = m0 >> 12, l0 = m0 & (NL - 1);
        float* dst = g_kpT + ((size_t)bh * NM + n0 + tid) * NL + l0;
#pragma unroll
        for (int j = 0; j < 32; j++) {
            float4 o;
            o.x = st[(4 * j + 0) * 129 + tid];
            o.y = st[(4 * j + 1) * 129 + tid];
            o.z = st[(4 * j + 2) * 129 + tid];
            o.w = st[(4 * j + 3) * 129 + tid];
            *(float4*)(dst + 4 * j) = o;
        }
    } else if (MODE == 2) {
        const int region = n0 / 768;               // 0=q, 1=k, 2=v
        if (region < 2) {
            const int h = ((n0 % 768) >> 6) + wn;
#pragma unroll
            for (int mi = 0; mi < 4; mi++) {
#pragma unroll
                for (int rr = 0; rr < 2; rr++) {
                    int r = m0 + wm * 64 + mi * 16 + rr * 8 + lrow;
                    int b = r >> 12, l = r & (NL - 1);
                    float* dst = g_qk +
                        ((size_t)region * NRH + (size_t)(b * NH + h) * NL + l) * ND;
#pragma unroll
                    for (int ni = 0; ni < 8; ni++) {
                        int d = ni * 8 + lcol;
                        int col = n0 + wn * 64 + d;
                        float v0 = rna(acc[mi][ni][rr * 2]     + bias[col]);
                        float v1 = rna(acc[mi][ni][rr * 2 + 1] + bias[col + 1]);
                        *(float2*)(dst + d) = make_float2(v0, v1);
                    }
                }
            }
        } else {
            // v transposed -> g_vT[bh][d][l], staged through smem
            float* st = (float*)dynsm;   // [128 tok][129]
#pragma unroll
            for (int mi = 0; mi < 4; mi++) {
#pragma unroll
                for (int rr = 0; rr < 2; rr++) {
                    int row = wm * 64 + mi * 16 + rr * 8 + lrow;
#pragma unroll
                    for (int ni = 0; ni < 8; ni++) {
                        int cl = wn * 64 + ni * 8 + lcol;
                        int col = n0 + cl;
                        st[row * 129 + cl]     = rna(acc[mi][ni][rr * 2]     + bias[col]);
                        st[row * 129 + cl + 1] = rna(acc[mi][ni][rr * 2 + 1] + bias[col + 1]);
                    }
                }
            }
            __syncthreads();
            int b = m0 >> 12, l0 = m0 & (NL - 1);
            int head = ((n0 - 1536) >> 6) + (tid >> 6);
            float* dst = g_vT + ((size_t)(b * NH + head) * 128 + (tid & 63)) * NL + l0;
#pragma unroll
            for (int j = 0; j < 32; j++) {
                float4 o;
                o.x = st[(4 * j + 0) * 129 + tid];
                o.y = st[(4 * j + 1) * 129 + tid];
                o.z = st[(4 * j + 2) * 129 + tid];
                o.w = st[(4 * j + 3) * 129 + tid];
                *(float4*)(dst + 4 * j) = o;
            }
        }
    } else if (MODE == 6) {
        const int bh = blockIdx.z >> 3;
        float* dst = g_kv + (size_t)bh * NM * 128;
#pragma unroll
        for (int mi = 0; mi < 4; mi++) {
#pragma unroll
            for (int ni = 0; ni < 8; ni++) {
                int colx = wn * 64 + ni * 8 + lcol;
                int r0 = m0 + wm * 64 + mi * 16 + lrow;
                atomicAdd(dst + (size_t)r0 * 128 + colx,           acc[mi][ni][0]);
                atomicAdd(dst + (size_t)r0 * 128 + colx + 1,       acc[mi][ni][1]);
                atomicAdd(dst + (size_t)(r0 + 8) * 128 + colx,     acc[mi][ni][2]);
                atomicAdd(dst + (size_t)(r0 + 8) * 128 + colx + 1, acc[mi][ni][3]);
            }
        }
    } else if (MODE == 3) {
        if (wn == 1 && (lid & 3) == 0) {
#pragma unroll
            for (int mi = 0; mi < 4; mi++)
#pragma unroll
                for (int rr = 0; rr < 2; rr++)
                    den_sh[wm * 64 + mi * 16 + rr * 8 + lrow] = acc[mi][0][rr * 2];
        }
        __syncthreads();
        if (wn == 0) {
            const int bh = blockIdx.z;
            const int b = bh / NH, h = bh - b * NH;
#pragma unroll
            for (int mi = 0; mi < 4; mi++) {
#pragma unroll
                for (int rr = 0; rr < 2; rr++) {
                    int rloc = wm * 64 + mi * 16 + rr * 8 + lrow;
                    int token = b * NL + m0 + rloc;
                    float inv = 1.0f / den_sh[rloc];
                    float* dst = g_att + (size_t)token * NDIM + h * ND;
#pragma unroll
                    for (int ni = 0; ni < 8; ni++) {
                        int d = ni * 8 + lcol;
                        float v0 = rna(acc[mi][ni][rr * 2]     * inv);
                        float v1 = rna(acc[mi][ni][rr * 2 + 1] * inv);
                        *(float2*)(dst + d) = make_float2(v0, v1);
                    }
                }
            }
        }
    }
}

// ---------------- launch ----------------
extern "C" void kernel_launch(void* const* d_in, const int* in_sizes, int n_in,
                              void* d_out, int out_size)
{
    const float* x        = (const float*)d_in[0];
    const float* qkv_w    = (const float*)d_in[1];
    const float* qkv_b    = (const float*)d_in[2];
    const float* proj_w   = (const float*)d_in[3];
    const float* proj_b   = (const float*)d_in[4];
    const float* proj_mat = (const float*)d_in[5];
    float* out = (float*)d_out;

    float *xr_p, *wr_p, *pwr_p, *pmr_p, *qk_p, *qp_p, *kv_p, *kvt_p, *att_p;
    cudaGetSymbolAddress((void**)&xr_p,  g_xr);
    cudaGetSymbolAddress((void**)&wr_p,  g_wr);
    cudaGetSymbolAddress((void**)&pwr_p, g_pwr);
    cudaGetSymbolAddress((void**)&pmr_p, g_pmr);
    cudaGetSymbolAddress((void**)&qk_p,  g_qk);
    cudaGetSymbolAddress((void**)&qp_p,  g_qp);
    cudaGetSymbolAddress((void**)&kv_p,  g_kv);
    cudaGetSymbolAddress((void**)&kvt_p, g_kvT);
    cudaGetSymbolAddress((void**)&att_p, g_att);

    const int SMEM_GEMM = 3 * 32768 + 1024;
    cudaFuncSetAttribute(mma_gemm<0>, cudaFuncAttributeMaxDynamicSharedMemorySize, SMEM_GEMM);
    cudaFuncSetAttribute(mma_gemm<2>, cudaFuncAttributeMaxDynamicSharedMemorySize, SMEM_GEMM);
    cudaFuncSetAttribute(mma_gemm<3>, cudaFuncAttributeMaxDynamicSharedMemorySize, SMEM_GEMM);
    cudaFuncSetAttribute(mma_gemm<4>, cudaFuncAttributeMaxDynamicSharedMemorySize, SMEM_GEMM);
    cudaFuncSetAttribute(mma_gemm<5>, cudaFuncAttributeMaxDynamicSharedMemorySize, SMEM_GEMM);
    cudaFuncSetAttribute(mma_gemm<6>, cudaFuncAttributeMaxDynamicSharedMemorySize, SMEM_GEMM);

    // zero kv accumulator; init vT ones/zero rows
    const int kvn = NB * NH * NM * 128;
    zero_kernel<<<(kvn + 255) / 256, 256>>>(kv_p, kvn);
    initvt_kernel<<<4096, 256>>>();

    // tf32-round raw inputs
    rna4_kernel<<<4096, 256>>>(x,        xr_p,  NTOK * NDIM / 4);
    rna4_kernel<<<1024, 256>>>(qkv_w,    wr_p,  2304 * NDIM / 4);
    rna4_kernel<<< 512, 256>>>(proj_w,   pwr_p, NDIM * NDIM / 4);
    rna4_kernel<<<  16, 256>>>(proj_mat, pmr_p, NM * ND / 4);

    // K1: qkv = x @ qkv_w^T + b; scatter q,k rounded + v^T rounded
    mma_gemm<2><<<dim3(18, NTOK / 128), 128, SMEM_GEMM>>>(
        xr_p, NDIM, 0, wr_p, NDIM, 0, nullptr, 0, qkv_b, NDIM);

    // K2-q: q_p -> g_qp (rounded)
    mma_gemm<4><<<dim3(2, NRH / 128), 128, SMEM_GEMM>>>(
        qk_p, ND, 0, pmr_p, ND, 0, nullptr, 0, nullptr, ND);
    // K2-k: k_p -> g_kpT (rounded, transposed)
    mma_gemm<5><<<dim3(2, NRH / 128), 128, SMEM_GEMM>>>(
        qk_p + (size_t)NRH * ND, ND, 0, pmr_p, ND, 0, nullptr, 0, nullptr, ND);

    // K3: kv[bh] = kpT · vT^T  (tensor cores, split-K=8, atomic fp32)
    mma_gemm<6><<<dim3(1, 2, NB * NH * 8), 128, SMEM_GEMM>>>(
        nullptr, NL, 0, nullptr, NL, 0, nullptr, 0, nullptr, 512);

    // kv -> kvT (rounded)
    kvt_kernel<<<NB * NH, 256>>>();

    // K4: att = (q_p @ kv) / den -> g_att (rounded); z = bh
    mma_gemm<3><<<dim3(1, NL / 128, NB * NH), 128, SMEM_GEMM>>>(
        qp_p, NM, (size_t)NL * NM, kvt_p, NM, (size_t)128 * NM,
        nullptr, 0, nullptr, NM);

    // K5: out = att @ proj_w^T + proj_b
    mma_gemm<0><<<dim3(NDIM / 128, NTOK / 128), 128, SMEM_GEMM>>>(
        att_p, NDIM, 0, pwr_p, NDIM, 0, out, NDIM, proj_b, NDIM);
}